// round 3
// baseline (speedup 1.0000x reference)
#include <cuda_runtime.h>
#include <math.h>

#define NIMG 512
#define IMG_ELEMS (64*64*32)   // 131072 floats per "image" (bg slice)

// ---- scratch (device globals; allocation-free rule) ----
__device__ float g_x2[67108864];        // 512 * 131072, conv output
__device__ float g_sh[NIMG*64*32];      // sigmoid(x_h)
__device__ float g_sw[NIMG*64*32];      // sigmoid(x_w)
__device__ float g_sum[NIMG*32];        // gated sum   (GN)
__device__ float g_sumsq[NIMG*32];      // gated sumsq (GN)
__device__ float g_colsum[NIMG*32];     // x2 channel sums (for x21 softmax)
__device__ float g_mu[NIMG*32];
__device__ float g_rs[NIMG*32];
__device__ float g_x21[NIMG*32];
__device__ float g_x11[32];

// ---- packed f32x2 helpers (FFMA2: only reachable via explicit PTX) ----
__device__ __forceinline__ unsigned long long pk2(float a, float b) {
    unsigned long long r;
    asm("mov.b64 %0, {%1, %2};" : "=l"(r) : "f"(a), "f"(b));
    return r;
}
__device__ __forceinline__ void upk2(unsigned long long v, float& a, float& b) {
    asm("mov.b64 {%0, %1}, %2;" : "=f"(a), "=f"(b) : "l"(v));
}
__device__ __forceinline__ unsigned long long fma2(unsigned long long a,
                                                   unsigned long long b,
                                                   unsigned long long c) {
    unsigned long long d;
    asm("fma.rn.f32x2 %0, %1, %2, %3;" : "=l"(d) : "l"(a), "l"(b), "l"(c));
    return d;
}

// ===================== K1: row/col means + 32x32 matmul + sigmoid =====================
__global__ void __launch_bounds__(256) k1_means(const float* __restrict__ x,
                                                const float* __restrict__ w1,
                                                const float* __restrict__ b1) {
    int g = blockIdx.x;
    const float* A = x + (size_t)g * IMG_ELEMS;
    __shared__ float s_xh[2048], s_xw[2048], s_w1[1024];
    int tid = threadIdx.x, lane = tid & 31, wid = tid >> 5;

    if (tid < 32) {  // zero atomic targets for this image (graph replays re-zero)
        g_sum[g*32+tid] = 0.f; g_sumsq[g*32+tid] = 0.f; g_colsum[g*32+tid] = 0.f;
    }
    for (int i = tid; i < 1024; i += 256) s_w1[i] = w1[i];

    // x_h: mean over w. warp = one h row, lane = channel (coalesced)
    for (int h = wid; h < 64; h += 8) {
        float acc = 0.f;
        #pragma unroll 8
        for (int w = 0; w < 64; w++) acc += A[(h*64 + w)*32 + lane];
        s_xh[h*32 + lane] = acc * (1.f/64.f);
    }
    // x_w: mean over h. warp = one w column (L2-resident second pass)
    for (int w = wid; w < 64; w += 8) {
        float acc = 0.f;
        #pragma unroll 8
        for (int h = 0; h < 64; h++) acc += A[(h*64 + w)*32 + lane];
        s_xw[w*32 + lane] = acc * (1.f/64.f);
    }
    __syncthreads();

    // 128 rows (64 h + 64 w) x 32 outputs; sigmoid; store
    for (int i = tid; i < 4096; i += 256) {
        int row = i >> 5, d = i & 31;
        const float* v = (row < 64) ? &s_xh[row*32] : &s_xw[(row-64)*32];
        float acc = b1[d];
        #pragma unroll
        for (int c = 0; c < 32; c++) acc = fmaf(v[c], s_w1[c*32 + d], acc);
        float s = 1.f / (1.f + expf(-acc));
        if (row < 64) g_sh[(g*64 + row)*32 + d] = s;
        else          g_sw[(g*64 + (row-64))*32 + d] = s;
    }
}

// ===================== K2: 3x3 conv (SAME) + colsum + gated GN stats =====================
// Tile: 4 output rows x 64 cols x 32ch per block. 8 warps; warp owns 32 pixels; lane = out channel d.
// Math via packed fp32 (fma.rn.f32x2 -> FFMA2): 2x fp32 throughput, bit-exact per element.
__global__ void __launch_bounds__(256) k2_conv(const float* __restrict__ x,
                                               const float* __restrict__ w3,
                                               const float* __restrict__ b3) {
    int g = blockIdx.y, tile = blockIdx.x, h0 = tile * 4;
    const float* A = x + (size_t)g * IMG_ELEMS;
    extern __shared__ float sm[];
    float* s_w   = sm;              // 9216  : w3[kh][kw][ci][d]
    float* s_in  = sm + 9216;       // 6*66*32 = 12672 : halo tile, zero-padded cols 0/65
    float* s_red = s_in + 12672;    // 3*8*32 = 768
    int tid = threadIdx.x, lane = tid & 31, wid = tid >> 5;

    for (int i = tid; i < 9216; i += 256) s_w[i] = w3[i];
    for (int i = tid; i < (6*66*32)/4; i += 256) {
        int idx = i * 4;
        int r   = idx / (66*32);
        int rem = idx - r * (66*32);
        int col = rem >> 5;
        int ci  = rem & 31;
        float4 v = make_float4(0.f, 0.f, 0.f, 0.f);
        int h = h0 - 1 + r;
        if (col >= 1 && col <= 64 && h >= 0 && h < 64)
            v = *(const float4*)&A[(h*64 + (col-1))*32 + ci];
        *(float4*)&s_in[idx] = v;
    }
    __syncthreads();

    // f32x2 accumulators: lo/hi accumulate even/odd ci partial sums per pixel
    unsigned long long accp[32];
    #pragma unroll
    for (int j = 0; j < 32; j++) accp[j] = 0ULL;
    int hl = wid >> 1, wbase = (wid & 1) * 32;

    for (int c0 = 0; c0 < 32; c0 += 4) {       // ci chunks of 4
        unsigned long long wp[9][2];           // packed {w[ci0],w[ci1]}, {w[ci2],w[ci3]}
        #pragma unroll
        for (int k = 0; k < 9; k++) {
            wp[k][0] = pk2(s_w[k*1024 + (c0+0)*32 + lane], s_w[k*1024 + (c0+1)*32 + lane]);
            wp[k][1] = pk2(s_w[k*1024 + (c0+2)*32 + lane], s_w[k*1024 + (c0+3)*32 + lane]);
        }
        #pragma unroll
        for (int j2 = 0; j2 < 32; j2++) {      // pixels: 1 LDS.128 broadcast -> 2 FFMA2
            int wq = wbase + j2;
            unsigned long long a = accp[j2];
            #pragma unroll
            for (int kh = 0; kh < 3; kh++)
                #pragma unroll
                for (int kw = 0; kw < 3; kw++) {
                    const ulonglong2 a2 =
                        *(const ulonglong2*)&s_in[((hl+kh)*66 + (wq+kw))*32 + c0];
                    int k = kh*3 + kw;
                    a = fma2(a2.x, wp[k][0], a);
                    a = fma2(a2.y, wp[k][1], a);
                }
            accp[j2] = a;
        }
    }

    // write x2 (+b3) and per-warp channel sums
    float b3v = b3[lane];
    float csum = 0.f;
    int h = h0 + hl;
    #pragma unroll
    for (int j2 = 0; j2 < 32; j2++) {
        float lo, hi;
        upk2(accp[j2], lo, hi);
        float v = (lo + hi) + b3v;
        g_x2[((size_t)g*4096 + h*64 + wbase + j2)*32 + lane] = v;
        csum += v;
    }

    // gated GN stats from the same smem tile (lane = channel)
    float shv = g_sh[(g*64 + h)*32 + lane];
    float s1 = 0.f, s2 = 0.f;
    #pragma unroll
    for (int j2 = 0; j2 < 32; j2++) {
        int wq = wbase + j2;
        float a  = s_in[((hl+1)*66 + (wq+1))*32 + lane];
        float gt = a * shv * g_sw[(g*64 + wq)*32 + lane];
        s1 += gt; s2 += gt*gt;
    }
    s_red[(0*8 + wid)*32 + lane] = csum;
    s_red[(1*8 + wid)*32 + lane] = s1;
    s_red[(2*8 + wid)*32 + lane] = s2;
    __syncthreads();
    if (wid < 3) {
        float t = 0.f;
        #pragma unroll
        for (int k = 0; k < 8; k++) t += s_red[(wid*8 + k)*32 + lane];
        float* dst = (wid == 0) ? g_colsum : (wid == 1) ? g_sum : g_sumsq;
        atomicAdd(&dst[g*32 + lane], t);
    }
}

// ===================== K3: mu/rsqrt, softmax(x21), softmax(gn_beta)=x11 =====================
__global__ void k3_finalize(const float* __restrict__ gn_beta) {
    int g = blockIdx.x, t = threadIdx.x;
    float mu  = g_sum[g*32 + t] * (1.f/4096.f);
    float var = g_sumsq[g*32 + t] * (1.f/4096.f) - mu*mu;
    g_mu[g*32 + t] = mu;
    g_rs[g*32 + t] = rsqrtf(var + 1e-3f);

    float m = g_colsum[g*32 + t] * (1.f/4096.f);
    float mx = m;
    #pragma unroll
    for (int o = 16; o > 0; o >>= 1) mx = fmaxf(mx, __shfl_xor_sync(0xffffffffu, mx, o));
    float e = expf(m - mx);
    float se = e;
    #pragma unroll
    for (int o = 16; o > 0; o >>= 1) se += __shfl_xor_sync(0xffffffffu, se, o);
    g_x21[g*32 + t] = e / se;

    if (g == 0) {  // x11 = softmax(mean(x1)) = softmax(gn_beta), same for all images
        float bb = gn_beta[t];
        float mx2 = bb;
        #pragma unroll
        for (int o = 16; o > 0; o >>= 1) mx2 = fmaxf(mx2, __shfl_xor_sync(0xffffffffu, mx2, o));
        float e2 = expf(bb - mx2);
        float s2 = e2;
        #pragma unroll
        for (int o = 16; o > 0; o >>= 1) s2 += __shfl_xor_sync(0xffffffffu, s2, o);
        g_x11[t] = e2 / s2;
    }
}

// ===================== K4: weights (flat einsum) + sigmoid + output =====================
__global__ void __launch_bounds__(1024) k4_weights_out(const float* __restrict__ x,
                                                       const float* __restrict__ gn_gamma,
                                                       const float* __restrict__ gn_beta,
                                                       float* __restrict__ out) {
    int g = blockIdx.x, tid = threadIdx.x;
    const float* A  = x    + (size_t)g * IMG_ELEMS;
    const float* X2 = g_x2 + (size_t)g * IMG_ELEMS;
    __shared__ float s_wt[4096];
    __shared__ float s_sh[2048], s_sw[2048];
    __shared__ float s_x11[32], s_x21[32], s_mu[32], s_rs[32], s_gb[64];
    for (int i = tid; i < 2048; i += 1024) {
        s_sh[i] = g_sh[g*2048 + i];
        s_sw[i] = g_sw[g*2048 + i];
    }
    if (tid < 32) {
        s_x11[tid] = g_x11[tid];
        s_x21[tid] = g_x21[g*32 + tid];
        s_mu[tid]  = g_mu[g*32 + tid];
        s_rs[tid]  = g_rs[g*32 + tid];
        s_gb[tid]      = gn_gamma[tid];
        s_gb[32 + tid] = gn_beta[tid];
    }
    __syncthreads();

    // weights[l] = sum_c x11[c]*x2flat[c*4096+l] + x21[c]*x1flat[c*4096+l]
    // x1flat recomputed from A on the fly. Fully coalesced (lane <-> l).
    #pragma unroll
    for (int k = 0; k < 4; k++) {
        int l  = tid + k*1024;
        int cc = l & 31;
        int q  = l >> 5;          // 0..127
        int w  = q & 63;
        float rs = s_rs[cc], mu = s_mu[cc], gam = s_gb[cc], bet = s_gb[32 + cc];
        float swv = s_sw[w*32 + cc];
        float acc = 0.f;
        #pragma unroll 8
        for (int c = 0; c < 32; c++) {
            int f = c*4096 + l;
            float x2v = X2[f];
            float a   = A[f];
            int h = 2*c + (q >> 6);
            float gt  = a * s_sh[h*32 + cc] * swv;
            float x1v = (gt - mu) * rs * gam + bet;
            acc += s_x11[c]*x2v + s_x21[c]*x1v;
        }
        s_wt[l] = 1.f / (1.f + expf(-acc));   // sigmoid(weights)
    }
    __syncthreads();

    // out = gx * sigmoid(weights)  (weights broadcast over 32 channels)
    const float4* A4 = (const float4*)A;
    float4* O4 = (float4*)(out + (size_t)g * IMG_ELEMS);
    for (int i = tid; i < IMG_ELEMS/4; i += 1024) {
        float sg = s_wt[i >> 3];   // (i*4) >> 5
        float4 a4 = A4[i];
        float4 o;
        o.x = a4.x*sg; o.y = a4.y*sg; o.z = a4.z*sg; o.w = a4.w*sg;
        O4[i] = o;
    }
}

// ===================== launch =====================
extern "C" void kernel_launch(void* const* d_in, const int* in_sizes, int n_in,
                              void* d_out, int out_size) {
    const float* x     = (const float*)d_in[0];
    const float* w1    = (const float*)d_in[1];
    const float* b1    = (const float*)d_in[2];
    const float* w3    = (const float*)d_in[3];
    const float* b3    = (const float*)d_in[4];
    const float* gamma = (const float*)d_in[5];
    const float* beta  = (const float*)d_in[6];
    float* out = (float*)d_out;

    const int k2_smem = (9216 + 12672 + 768) * 4;   // 90624 B
    cudaFuncSetAttribute(k2_conv, cudaFuncAttributeMaxDynamicSharedMemorySize, k2_smem);

    k1_means<<<NIMG, 256>>>(x, w1, b1);
    k2_conv<<<dim3(16, NIMG), 256, k2_smem>>>(x, w3, b3);
    k3_finalize<<<NIMG, 32>>>(beta);
    k4_weights_out<<<NIMG, 1024>>>(x, gamma, beta, out);
}

// round 8
// speedup vs baseline: 1.1670x; 1.1670x over previous
#include <cuda_runtime.h>
#include <cuda_bf16.h>
#include <cstdint>
#include <math.h>

typedef unsigned int u32;

#define NIMG 512
#define IMG_ELEMS (64*64*32)

// ---- scratch (device globals; allocation-free rule) ----
__device__ float g_x2[67108864];        // conv output (+b3)
__device__ float g_sh[NIMG*64*32];
__device__ float g_sw[NIMG*64*32];
__device__ float g_sum[NIMG*32];
__device__ float g_sumsq[NIMG*32];
__device__ float g_colsum[NIMG*32];
__device__ float g_mu[NIMG*32];
__device__ float g_rs[NIMG*32];
__device__ float g_x21[NIMG*32];
__device__ float g_x11[32];
// W transposed [d][k], bf16 hi/lo, row stride 328 bf16 (=164 u32, conflict-free)
__device__ __align__(16) unsigned short g_whi[32*328];
__device__ __align__(16) unsigned short g_wlo[32*328];

__device__ __forceinline__ u32 pack_bf(float x, float y) {
    u32 a = (u32)__bfloat16_as_ushort(__float2bfloat16(x));
    u32 b = (u32)__bfloat16_as_ushort(__float2bfloat16(y));
    return a | (b << 16);
}
// m16n8k16 row.col bf16 -> f32 accumulate (HMMA.16816; valid on base sm_103)
__device__ __forceinline__ void mma_bf16(float* c, const u32* a, const u32* b) {
    asm volatile("mma.sync.aligned.m16n8k16.row.col.f32.bf16.bf16.f32 {%0,%1,%2,%3}, {%4,%5,%6,%7}, {%8,%9}, {%0,%1,%2,%3};" : "+f"(c[0]), "+f"(c[1]), "+f"(c[2]), "+f"(c[3]) : "r"(a[0]), "r"(a[1]), "r"(a[2]), "r"(a[3]), "r"(b[0]), "r"(b[1]));
}

// ===================== K0: transpose + bf16-split conv weights =====================
// g_whi/g_wlo[d*328 + k], k = (kh*3+kw)*32 + ci, k in [0,288), pad zeros to 328.
__global__ void k0_prep(const float* __restrict__ w3) {
    for (int idx = threadIdx.x; idx < 32*328; idx += blockDim.x) {
        int d = idx / 328;
        int k = idx % 328;
        float v = (k < 288) ? w3[k*32 + d] : 0.f;
        __nv_bfloat16 hb = __float2bfloat16(v);
        float lo = v - __bfloat162float(hb);
        g_whi[idx] = __bfloat16_as_ushort(hb);
        g_wlo[idx] = __bfloat16_as_ushort(__float2bfloat16(lo));
    }
}

// ===================== K1: row/col means + 32x32 matmul + sigmoid (+ zero stats) =====================
__global__ void __launch_bounds__(256) k1_means(const float* __restrict__ x,
                                                const float* __restrict__ w1,
                                                const float* __restrict__ b1) {
    int g = blockIdx.x;
    const float* A = x + (size_t)g * IMG_ELEMS;
    __shared__ float s_xh[2048];
    __shared__ float s_xw[2048];
    __shared__ float s_w1[1024];
    int tid = threadIdx.x;
    int lane = tid & 31;
    int wid = tid >> 5;

    if (tid < 32) {
        g_sum[g*32+tid] = 0.f;
        g_sumsq[g*32+tid] = 0.f;
        g_colsum[g*32+tid] = 0.f;
    }
    for (int i = tid; i < 1024; i += 256) s_w1[i] = w1[i];

    for (int h = wid; h < 64; h += 8) {
        float acc = 0.f;
        for (int w = 0; w < 64; w++) acc += A[(h*64 + w)*32 + lane];
        s_xh[h*32 + lane] = acc * (1.f/64.f);
    }
    for (int w = wid; w < 64; w += 8) {
        float acc = 0.f;
        for (int h = 0; h < 64; h++) acc += A[(h*64 + w)*32 + lane];
        s_xw[w*32 + lane] = acc * (1.f/64.f);
    }
    __syncthreads();
    for (int i = tid; i < 4096; i += 256) {
        int row = i >> 5;
        int d = i & 31;
        const float* v = (row < 64) ? (s_xh + row*32) : (s_xw + (row-64)*32);
        float acc = b1[d];
        for (int c = 0; c < 32; c++) acc = fmaf(v[c], s_w1[c*32 + d], acc);
        float s = 1.f / (1.f + expf(-acc));
        if (row < 64) g_sh[(g*64 + row)*32 + d] = s;
        else g_sw[(g*64 + (row-64))*32 + d] = s;
    }
}

// ===================== K2: HMMA bf16-split conv + colsum + gated GN stats =====================
// Block: 4 output rows x 64 cols x 32ch. 8 warps; warp = 32-pixel strip (2 m16 tiles x 4 n8 tiles).
// smem byte offsets:
#define SM_WH  0
#define SM_WL  20992
#define SM_INH 41984
#define SM_INL 73664
#define SM_OUT 105344
#define SM_RED 140160
#define SM_TOTAL 143360
// input planes: [6 rows][66 cols][32 ci bf16], col stride 20 u32 (40 bf16)

__global__ void __launch_bounds__(256) k2_conv(const float* __restrict__ x,
                                               const float* __restrict__ b3) {
    int gimg = blockIdx.y;
    int h0 = blockIdx.x * 4;
    const float* A = x + (size_t)gimg * IMG_ELEMS;
    extern __shared__ char sm[];
    u32* inh32 = (u32*)(sm + SM_INH);
    u32* inl32 = (u32*)(sm + SM_INL);
    const u32* wh32 = (const u32*)(sm + SM_WH);
    const u32* wl32 = (const u32*)(sm + SM_WL);
    float* s_out = (float*)(sm + SM_OUT);
    float* s_red = (float*)(sm + SM_RED);
    int tid = threadIdx.x;
    int lane = tid & 31;
    int wid = tid >> 5;

    // load W planes (pre-split/transposed): 2 x 20992 B
    {
        const float4* srcH = (const float4*)g_whi;
        const float4* srcL = (const float4*)g_wlo;
        float4* dstH = (float4*)(sm + SM_WH);
        float4* dstL = (float4*)(sm + SM_WL);
        for (int i = tid; i < 1312; i += 256) {
            dstH[i] = srcH[i];
            dstL[i] = srcL[i];
        }
    }
    // fill halo input tile (rows h0-1 .. h0+4), bf16 hi/lo planes
    for (int i = tid; i < (6*66*32)/4; i += 256) {
        int idx = i * 4;
        int r = idx / 2112;
        int rem = idx - r*2112;
        int col = rem >> 5;
        int ci = rem & 31;
        int h = h0 - 1 + r;
        float4 v = make_float4(0.f, 0.f, 0.f, 0.f);
        if (col >= 1 && col <= 64 && h >= 0 && h < 64)
            v = *(const float4*)(A + (h*64 + col - 1)*32 + ci);
        __nv_bfloat16 h0b = __float2bfloat16(v.x);
        __nv_bfloat16 h1b = __float2bfloat16(v.y);
        __nv_bfloat16 h2b = __float2bfloat16(v.z);
        __nv_bfloat16 h3b = __float2bfloat16(v.w);
        float l0 = v.x - __bfloat162float(h0b);
        float l1 = v.y - __bfloat162float(h1b);
        float l2 = v.z - __bfloat162float(h2b);
        float l3 = v.w - __bfloat162float(h3b);
        int wbase = (r*66 + col)*20 + (ci >> 1);
        inh32[wbase]     = ((u32)__bfloat16_as_ushort(h0b)) | (((u32)__bfloat16_as_ushort(h1b)) << 16);
        inh32[wbase + 1] = ((u32)__bfloat16_as_ushort(h2b)) | (((u32)__bfloat16_as_ushort(h3b)) << 16);
        inl32[wbase]     = pack_bf(l0, l1);
        inl32[wbase + 1] = pack_bf(l2, l3);
    }
    __syncthreads();

    int hl = wid >> 1;            // output row within tile (0..3)
    int wbase = (wid & 1) * 32;   // col base of this warp's 32-pixel strip
    int g = lane >> 2;            // fragment group
    int t = lane & 3;

    float acc[2][4][4];
    for (int m = 0; m < 2; m++)
        for (int n = 0; n < 4; n++)
            for (int r = 0; r < 4; r++) acc[m][n][r] = 0.f;

    for (int tap = 0; tap < 9; tap++) {
        int kh = tap / 3;
        int kw = tap - kh*3;
        #pragma unroll
        for (int half = 0; half < 2; half++) {
            int ciw = half * 8;   // ci0/2 in u32 words
            u32 ah[2][4], al[2][4];
            #pragma unroll
            for (int m = 0; m < 2; m++) {
                int base = ((hl + kh)*66 + wbase + m*16 + g + kw)*20 + ciw + t;
                ah[m][0] = inh32[base];
                ah[m][1] = inh32[base + 160];   // pixel col +8 (8*20)
                ah[m][2] = inh32[base + 4];     // k +8 (4 words)
                ah[m][3] = inh32[base + 164];
                al[m][0] = inl32[base];
                al[m][1] = inl32[base + 160];
                al[m][2] = inl32[base + 4];
                al[m][3] = inl32[base + 164];
            }
            u32 bh[4][2], bl[4][2];
            #pragma unroll
            for (int n = 0; n < 4; n++) {
                int wb = (n*8 + g)*164 + tap*16 + ciw + t;
                bh[n][0] = wh32[wb];
                bh[n][1] = wh32[wb + 4];
                bl[n][0] = wl32[wb];
                bl[n][1] = wl32[wb + 4];
            }
            #pragma unroll
            for (int m = 0; m < 2; m++) {
                #pragma unroll
                for (int n = 0; n < 4; n++) {
                    mma_bf16(acc[m][n], ah[m], bh[n]);
                    mma_bf16(acc[m][n], al[m], bh[n]);
                    mma_bf16(acc[m][n], ah[m], bl[n]);
                }
            }
        }
    }

    // stage D to smem: s_out[pix_in_tile * 34 + ch]
    #pragma unroll
    for (int m = 0; m < 2; m++) {
        #pragma unroll
        for (int n = 0; n < 4; n++) {
            int pix0 = hl*64 + wbase + m*16 + g;
            int ch = n*8 + 2*t;
            s_out[pix0*34 + ch]       = acc[m][n][0];
            s_out[pix0*34 + ch + 1]   = acc[m][n][1];
            s_out[(pix0+8)*34 + ch]   = acc[m][n][2];
            s_out[(pix0+8)*34 + ch+1] = acc[m][n][3];
        }
    }
    __syncthreads();

    // coalesced x2 write (+b3) + channel sums (lane = channel) — R2 pattern
    float b3v = b3[lane];
    float csum = 0.f;
    int hglob = h0 + hl;
    for (int j2 = 0; j2 < 32; j2++) {
        int pix = hl*64 + wbase + j2;
        float v = s_out[pix*34 + lane] + b3v;
        g_x2[((size_t)gimg*4096 + (size_t)hglob*64 + wbase + j2)*32 + lane] = v;
        csum += v;
    }

    // gated GN stats from the input tile (lane = channel) — R2 pattern
    float shv = g_sh[(gimg*64 + hglob)*32 + lane];
    const __nv_bfloat16* inh16 = (const __nv_bfloat16*)(sm + SM_INH);
    const __nv_bfloat16* inl16 = (const __nv_bfloat16*)(sm + SM_INL);
    float s1 = 0.f, s2 = 0.f;
    for (int j2 = 0; j2 < 32; j2++) {
        int wq = wbase + j2;
        int i16 = ((hl + 1)*66 + wq + 1)*40 + lane;
        float a = __bfloat162float(inh16[i16]) + __bfloat162float(inl16[i16]);
        float gt = a * shv * g_sw[(gimg*64 + wq)*32 + lane];
        s1 += gt;
        s2 += gt*gt;
    }
    s_red[(0*8 + wid)*32 + lane] = csum;
    s_red[(1*8 + wid)*32 + lane] = s1;
    s_red[(2*8 + wid)*32 + lane] = s2;
    __syncthreads();
    if (wid < 3) {
        float tsum = 0.f;
        for (int k = 0; k < 8; k++) tsum += s_red[(wid*8 + k)*32 + lane];
        float* dst = (wid == 0) ? g_colsum : (wid == 1) ? g_sum : g_sumsq;
        atomicAdd(dst + gimg*32 + lane, tsum);
    }
}

// ===================== K3: mu/rsqrt, softmax(x21), softmax(gn_beta)=x11 =====================
__global__ void k3_finalize(const float* __restrict__ gn_beta) {
    int g = blockIdx.x;
    int t = threadIdx.x;
    float mu  = g_sum[g*32 + t] * (1.f/4096.f);
    float var = g_sumsq[g*32 + t] * (1.f/4096.f) - mu*mu;
    g_mu[g*32 + t] = mu;
    g_rs[g*32 + t] = rsqrtf(var + 1e-3f);

    float m = g_colsum[g*32 + t] * (1.f/4096.f);
    float mx = m;
    for (int o = 16; o > 0; o >>= 1) mx = fmaxf(mx, __shfl_xor_sync(0xffffffffu, mx, o));
    float e = expf(m - mx);
    float se = e;
    for (int o = 16; o > 0; o >>= 1) se += __shfl_xor_sync(0xffffffffu, se, o);
    g_x21[g*32 + t] = e / se;

    if (g == 0) {
        float bb = gn_beta[t];
        float mx2 = bb;
        for (int o = 16; o > 0; o >>= 1) mx2 = fmaxf(mx2, __shfl_xor_sync(0xffffffffu, mx2, o));
        float e2 = expf(bb - mx2);
        float s2 = e2;
        for (int o = 16; o > 0; o >>= 1) s2 += __shfl_xor_sync(0xffffffffu, s2, o);
        g_x11[t] = e2 / s2;
    }
}

// ===================== K4: weights (flat einsum) + sigmoid + output =====================
__global__ void __launch_bounds__(1024) k4_weights_out(const float* __restrict__ x,
                                                       const float* __restrict__ gn_gamma,
                                                       const float* __restrict__ gn_beta,
                                                       float* __restrict__ out) {
    int g = blockIdx.x;
    int tid = threadIdx.x;
    const float* A  = x    + (size_t)g * IMG_ELEMS;
    const float* X2 = g_x2 + (size_t)g * IMG_ELEMS;
    __shared__ float s_wt[4096];
    __shared__ float s_sh[2048];
    __shared__ float s_sw[2048];
    __shared__ float s_x11[32];
    __shared__ float s_x21[32];
    __shared__ float s_mu[32];
    __shared__ float s_rs[32];
    __shared__ float s_gb[64];
    for (int i = tid; i < 2048; i += 1024) {
        s_sh[i] = g_sh[g*2048 + i];
        s_sw[i] = g_sw[g*2048 + i];
    }
    if (tid < 32) {
        s_x11[tid] = g_x11[tid];
        s_x21[tid] = g_x21[g*32 + tid];
        s_mu[tid]  = g_mu[g*32 + tid];
        s_rs[tid]  = g_rs[g*32 + tid];
        s_gb[tid]      = gn_gamma[tid];
        s_gb[32 + tid] = gn_beta[tid];
    }
    __syncthreads();

    for (int k = 0; k < 4; k++) {
        int l  = tid + k*1024;
        int cc = l & 31;
        int q  = l >> 5;
        int w  = q & 63;
        float rs = s_rs[cc];
        float mu = s_mu[cc];
        float gam = s_gb[cc];
        float bet = s_gb[32 + cc];
        float swv = s_sw[w*32 + cc];
        float acc = 0.f;
        for (int c = 0; c < 32; c++) {
            int f = c*4096 + l;
            float x2v = X2[f];
            float a   = A[f];
            int h = 2*c + (q >> 6);
            float gt  = a * s_sh[h*32 + cc] * swv;
            float x1v = (gt - mu) * rs * gam + bet;
            acc += s_x11[c]*x2v + s_x21[c]*x1v;
        }
        s_wt[l] = 1.f / (1.f + expf(-acc));
    }
    __syncthreads();

    const float4* A4 = (const float4*)A;
    float4* O4 = (float4*)(out + (size_t)g * IMG_ELEMS);
    for (int i = tid; i < IMG_ELEMS/4; i += 1024) {
        float sg = s_wt[i >> 3];
        float4 a4 = A4[i];
        float4 o;
        o.x = a4.x*sg;
        o.y = a4.y*sg;
        o.z = a4.z*sg;
        o.w = a4.w*sg;
        O4[i] = o;
    }
}

// ===================== launch =====================
extern "C" void kernel_launch(void* const* d_in, const int* in_sizes, int n_in,
                              void* d_out, int out_size) {
    const float* x     = (const float*)d_in[0];
    const float* w1    = (const float*)d_in[1];
    const float* b1    = (const float*)d_in[2];
    const float* w3    = (const float*)d_in[3];
    const float* b3    = (const float*)d_in[4];
    const float* gamma = (const float*)d_in[5];
    const float* beta  = (const float*)d_in[6];
    float* out = (float*)d_out;

    cudaFuncSetAttribute(k2_conv, cudaFuncAttributeMaxDynamicSharedMemorySize, SM_TOTAL);

    k0_prep<<<1, 256>>>(w3);
    k1_means<<<NIMG, 256>>>(x, w1, b1);
    k2_conv<<<dim3(16, NIMG), 256, SM_TOTAL>>>(x, b3);
    k3_finalize<<<NIMG, 32>>>(beta);
    k4_weights_out<<<NIMG, 1024>>>(x, gamma, beta, out);
}

// round 9
// speedup vs baseline: 1.4420x; 1.2356x over previous
#include <cuda_runtime.h>
#include <cuda_bf16.h>
#include <cstdint>
#include <math.h>

typedef unsigned int u32;

#define NIMG 512
#define IMG_ELEMS (64*64*32)

// ---- scratch (device globals; allocation-free rule) ----
__device__ float g_x2[67108864];        // conv output (+b3)
__device__ float g_sh[NIMG*64*32];
__device__ float g_sw[NIMG*64*32];
__device__ float g_sum[NIMG*32];
__device__ float g_sumsq[NIMG*32];
__device__ float g_colsum[NIMG*32];
__device__ float g_mu[NIMG*32];
__device__ float g_rs[NIMG*32];
__device__ float g_x21[NIMG*32];
__device__ float g_x11[32];
// W transposed [d][k], bf16 hi/lo, row stride 328 bf16 (=164 u32, conflict-free)
__device__ __align__(16) unsigned short g_whi[32*328];
__device__ __align__(16) unsigned short g_wlo[32*328];

__device__ __forceinline__ u32 pack_bf(float x, float y) {
    u32 a = (u32)__bfloat16_as_ushort(__float2bfloat16(x));
    u32 b = (u32)__bfloat16_as_ushort(__float2bfloat16(y));
    return a | (b << 16);
}
// m16n8k16 row.col bf16 -> f32 accumulate (HMMA.16816; valid on base sm_103)
__device__ __forceinline__ void mma_bf16(float* c, const u32* a, const u32* b) {
    asm volatile("mma.sync.aligned.m16n8k16.row.col.f32.bf16.bf16.f32 {%0,%1,%2,%3}, {%4,%5,%6,%7}, {%8,%9}, {%0,%1,%2,%3};" : "+f"(c[0]), "+f"(c[1]), "+f"(c[2]), "+f"(c[3]) : "r"(a[0]), "r"(a[1]), "r"(a[2]), "r"(a[3]), "r"(b[0]), "r"(b[1]));
}

// ===================== K0: transpose + bf16-split conv weights =====================
__global__ void k0_prep(const float* __restrict__ w3) {
    for (int idx = threadIdx.x; idx < 32*328; idx += blockDim.x) {
        int d = idx / 328;
        int k = idx % 328;
        float v = (k < 288) ? w3[k*32 + d] : 0.f;
        __nv_bfloat16 hb = __float2bfloat16(v);
        float lo = v - __bfloat162float(hb);
        g_whi[idx] = __bfloat16_as_ushort(hb);
        g_wlo[idx] = __bfloat16_as_ushort(__float2bfloat16(lo));
    }
}

// ===================== K1: row/col means + 32x32 matmul + sigmoid (+ zero stats) =====================
__global__ void __launch_bounds__(256) k1_means(const float* __restrict__ x,
                                                const float* __restrict__ w1,
                                                const float* __restrict__ b1) {
    int g = blockIdx.x;
    const float* A = x + (size_t)g * IMG_ELEMS;
    __shared__ float s_xh[2048];
    __shared__ float s_xw[2048];
    __shared__ float s_w1[1024];
    int tid = threadIdx.x;
    int lane = tid & 31;
    int wid = tid >> 5;

    if (tid < 32) {
        g_sum[g*32+tid] = 0.f;
        g_sumsq[g*32+tid] = 0.f;
        g_colsum[g*32+tid] = 0.f;
    }
    for (int i = tid; i < 1024; i += 256) s_w1[i] = w1[i];

    for (int h = wid; h < 64; h += 8) {
        float acc = 0.f;
        for (int w = 0; w < 64; w++) acc += A[(h*64 + w)*32 + lane];
        s_xh[h*32 + lane] = acc * (1.f/64.f);
    }
    for (int w = wid; w < 64; w += 8) {
        float acc = 0.f;
        for (int h = 0; h < 64; h++) acc += A[(h*64 + w)*32 + lane];
        s_xw[w*32 + lane] = acc * (1.f/64.f);
    }
    __syncthreads();
    for (int i = tid; i < 4096; i += 256) {
        int row = i >> 5;
        int d = i & 31;
        const float* v = (row < 64) ? (s_xh + row*32) : (s_xw + (row-64)*32);
        float acc = b1[d];
        for (int c = 0; c < 32; c++) acc = fmaf(v[c], s_w1[c*32 + d], acc);
        float s = 1.f / (1.f + expf(-acc));
        if (row < 64) g_sh[(g*64 + row)*32 + d] = s;
        else g_sw[(g*64 + (row-64))*32 + d] = s;
    }
}

// ===================== K2: HMMA bf16-split conv + colsum + gated GN stats =====================
// Block: 4 output rows x 64 cols x 32ch. 8 warps; warp = 32-pixel strip (2 m16 tiles x 4 n8 tiles).
// smem: s_out ALIASES the input-hi plane (live only after all input reads) -> 108416 B -> 2 CTAs/SM.
#define SM_WH  0
#define SM_WL  20992
#define SM_INH 41984
#define SM_INL 73664
#define SM_RED 105344
#define SM_TOTAL 108416
// input planes: [6 rows][66 cols][32 ci bf16], col stride 20 u32 (40 bf16)

__global__ void __launch_bounds__(256, 2) k2_conv(const float* __restrict__ x,
                                                  const float* __restrict__ b3) {
    int gimg = blockIdx.y;
    int h0 = blockIdx.x * 4;
    const float* A = x + (size_t)gimg * IMG_ELEMS;
    extern __shared__ char sm[];
    u32* inh32 = (u32*)(sm + SM_INH);
    u32* inl32 = (u32*)(sm + SM_INL);
    const u32* wh32 = (const u32*)(sm + SM_WH);
    const u32* wl32 = (const u32*)(sm + SM_WL);
    float* s_out = (float*)(sm + SM_INH);   // alias: valid only after input reads complete
    float* s_red = (float*)(sm + SM_RED);
    int tid = threadIdx.x;
    int lane = tid & 31;
    int wid = tid >> 5;

    // load W planes (pre-split/transposed): 2 x 20992 B
    {
        const float4* srcH = (const float4*)g_whi;
        const float4* srcL = (const float4*)g_wlo;
        float4* dstH = (float4*)(sm + SM_WH);
        float4* dstL = (float4*)(sm + SM_WL);
        for (int i = tid; i < 1312; i += 256) {
            dstH[i] = srcH[i];
            dstL[i] = srcL[i];
        }
    }
    // fill halo input tile (rows h0-1 .. h0+4), bf16 hi/lo planes
    for (int i = tid; i < (6*66*32)/4; i += 256) {
        int idx = i * 4;
        int r = idx / 2112;
        int rem = idx - r*2112;
        int col = rem >> 5;
        int ci = rem & 31;
        int h = h0 - 1 + r;
        float4 v = make_float4(0.f, 0.f, 0.f, 0.f);
        if (col >= 1 && col <= 64 && h >= 0 && h < 64)
            v = *(const float4*)(A + (h*64 + col - 1)*32 + ci);
        __nv_bfloat16 h0b = __float2bfloat16(v.x);
        __nv_bfloat16 h1b = __float2bfloat16(v.y);
        __nv_bfloat16 h2b = __float2bfloat16(v.z);
        __nv_bfloat16 h3b = __float2bfloat16(v.w);
        float l0 = v.x - __bfloat162float(h0b);
        float l1 = v.y - __bfloat162float(h1b);
        float l2 = v.z - __bfloat162float(h2b);
        float l3 = v.w - __bfloat162float(h3b);
        int wbase = (r*66 + col)*20 + (ci >> 1);
        inh32[wbase]     = ((u32)__bfloat16_as_ushort(h0b)) | (((u32)__bfloat16_as_ushort(h1b)) << 16);
        inh32[wbase + 1] = ((u32)__bfloat16_as_ushort(h2b)) | (((u32)__bfloat16_as_ushort(h3b)) << 16);
        inl32[wbase]     = pack_bf(l0, l1);
        inl32[wbase + 1] = pack_bf(l2, l3);
    }
    __syncthreads();

    int hl = wid >> 1;            // output row within tile (0..3)
    int wbase = (wid & 1) * 32;   // col base of this warp's 32-pixel strip
    int g = lane >> 2;            // fragment group
    int t = lane & 3;

    float acc[2][4][4];
    for (int m = 0; m < 2; m++)
        for (int n = 0; n < 4; n++)
            for (int r = 0; r < 4; r++) acc[m][n][r] = 0.f;

    for (int tap = 0; tap < 9; tap++) {
        int kh = tap / 3;
        int kw = tap - kh*3;
        #pragma unroll
        for (int half = 0; half < 2; half++) {
            int ciw = half * 8;   // ci0/2 in u32 words
            u32 ah[2][4], al[2][4];
            #pragma unroll
            for (int m = 0; m < 2; m++) {
                int base = ((hl + kh)*66 + wbase + m*16 + g + kw)*20 + ciw + t;
                ah[m][0] = inh32[base];
                ah[m][1] = inh32[base + 160];   // pixel col +8 (8*20)
                ah[m][2] = inh32[base + 4];     // k +8 (4 words)
                ah[m][3] = inh32[base + 164];
                al[m][0] = inl32[base];
                al[m][1] = inl32[base + 160];
                al[m][2] = inl32[base + 4];
                al[m][3] = inl32[base + 164];
            }
            u32 bh[4][2], bl[4][2];
            #pragma unroll
            for (int n = 0; n < 4; n++) {
                int wb = (n*8 + g)*164 + tap*16 + ciw + t;
                bh[n][0] = wh32[wb];
                bh[n][1] = wh32[wb + 4];
                bl[n][0] = wl32[wb];
                bl[n][1] = wl32[wb + 4];
            }
            #pragma unroll
            for (int m = 0; m < 2; m++) {
                #pragma unroll
                for (int n = 0; n < 4; n++) {
                    mma_bf16(acc[m][n], ah[m], bh[n]);
                    mma_bf16(acc[m][n], al[m], bh[n]);
                    mma_bf16(acc[m][n], ah[m], bl[n]);
                }
            }
        }
    }

    // gated GN stats FIRST (reads input planes; lane = channel)
    int hglob = h0 + hl;
    float shv = g_sh[(gimg*64 + hglob)*32 + lane];
    const __nv_bfloat16* inh16 = (const __nv_bfloat16*)(sm + SM_INH);
    const __nv_bfloat16* inl16 = (const __nv_bfloat16*)(sm + SM_INL);
    float s1 = 0.f, s2 = 0.f;
    for (int j2 = 0; j2 < 32; j2++) {
        int wq = wbase + j2;
        int i16 = ((hl + 1)*66 + wq + 1)*40 + lane;
        float a = __bfloat162float(inh16[i16]) + __bfloat162float(inl16[i16]);
        float gt = a * shv * g_sw[(gimg*64 + wq)*32 + lane];
        s1 += gt;
        s2 += gt*gt;
    }
    // all input reads done across ALL warps before s_out (alias) is written
    __syncthreads();

    // stage D to smem: s_out[pix_in_tile * 34 + ch]
    #pragma unroll
    for (int m = 0; m < 2; m++) {
        #pragma unroll
        for (int n = 0; n < 4; n++) {
            int pix0 = hl*64 + wbase + m*16 + g;
            int ch = n*8 + 2*t;
            s_out[pix0*34 + ch]       = acc[m][n][0];
            s_out[pix0*34 + ch + 1]   = acc[m][n][1];
            s_out[(pix0+8)*34 + ch]   = acc[m][n][2];
            s_out[(pix0+8)*34 + ch+1] = acc[m][n][3];
        }
    }
    __syncwarp();   // staging is warp-local; order cross-lane smem writes before reads

    // coalesced x2 write (+b3) + channel sums (lane = channel)
    float b3v = b3[lane];
    float csum = 0.f;
    for (int j2 = 0; j2 < 32; j2++) {
        int pix = hl*64 + wbase + j2;
        float v = s_out[pix*34 + lane] + b3v;
        g_x2[((size_t)gimg*4096 + (size_t)hglob*64 + wbase + j2)*32 + lane] = v;
        csum += v;
    }

    s_red[(0*8 + wid)*32 + lane] = csum;
    s_red[(1*8 + wid)*32 + lane] = s1;
    s_red[(2*8 + wid)*32 + lane] = s2;
    __syncthreads();
    if (wid < 3) {
        float tsum = 0.f;
        for (int k = 0; k < 8; k++) tsum += s_red[(wid*8 + k)*32 + lane];
        float* dst = (wid == 0) ? g_colsum : (wid == 1) ? g_sum : g_sumsq;
        atomicAdd(dst + gimg*32 + lane, tsum);
    }
}

// ===================== K3: mu/rsqrt, softmax(x21), softmax(gn_beta)=x11 =====================
__global__ void k3_finalize(const float* __restrict__ gn_beta) {
    int g = blockIdx.x;
    int t = threadIdx.x;
    float mu  = g_sum[g*32 + t] * (1.f/4096.f);
    float var = g_sumsq[g*32 + t] * (1.f/4096.f) - mu*mu;
    g_mu[g*32 + t] = mu;
    g_rs[g*32 + t] = rsqrtf(var + 1e-3f);

    float m = g_colsum[g*32 + t] * (1.f/4096.f);
    float mx = m;
    for (int o = 16; o > 0; o >>= 1) mx = fmaxf(mx, __shfl_xor_sync(0xffffffffu, mx, o));
    float e = expf(m - mx);
    float se = e;
    for (int o = 16; o > 0; o >>= 1) se += __shfl_xor_sync(0xffffffffu, se, o);
    g_x21[g*32 + t] = e / se;

    if (g == 0) {
        float bb = gn_beta[t];
        float mx2 = bb;
        for (int o = 16; o > 0; o >>= 1) mx2 = fmaxf(mx2, __shfl_xor_sync(0xffffffffu, mx2, o));
        float e2 = expf(bb - mx2);
        float s2 = e2;
        for (int o = 16; o > 0; o >>= 1) s2 += __shfl_xor_sync(0xffffffffu, s2, o);
        g_x11[t] = e2 / s2;
    }
}

// ===================== K4: weights (flat einsum) + sigmoid + output =====================
__global__ void __launch_bounds__(1024) k4_weights_out(const float* __restrict__ x,
                                                       const float* __restrict__ gn_gamma,
                                                       const float* __restrict__ gn_beta,
                                                       float* __restrict__ out) {
    int g = blockIdx.x;
    int tid = threadIdx.x;
    const float* A  = x    + (size_t)g * IMG_ELEMS;
    const float* X2 = g_x2 + (size_t)g * IMG_ELEMS;
    __shared__ float s_wt[4096];
    __shared__ float s_sh[2048];
    __shared__ float s_sw[2048];
    __shared__ float s_x11[32];
    __shared__ float s_x21[32];
    __shared__ float s_mu[32];
    __shared__ float s_rs[32];
    __shared__ float s_gb[64];
    for (int i = tid; i < 2048; i += 1024) {
        s_sh[i] = g_sh[g*2048 + i];
        s_sw[i] = g_sw[g*2048 + i];
    }
    if (tid < 32) {
        s_x11[tid] = g_x11[tid];
        s_x21[tid] = g_x21[g*32 + tid];
        s_mu[tid]  = g_mu[g*32 + tid];
        s_rs[tid]  = g_rs[g*32 + tid];
        s_gb[tid]      = gn_gamma[tid];
        s_gb[32 + tid] = gn_beta[tid];
    }
    __syncthreads();

    for (int k = 0; k < 4; k++) {
        int l  = tid + k*1024;
        int cc = l & 31;
        int q  = l >> 5;
        int w  = q & 63;
        float rs = s_rs[cc];
        float mu = s_mu[cc];
        float gam = s_gb[cc];
        float bet = s_gb[32 + cc];
        float swv = s_sw[w*32 + cc];
        float acc = 0.f;
        for (int c = 0; c < 32; c++) {
            int f = c*4096 + l;
            float x2v = X2[f];
            float a   = A[f];
            int h = 2*c + (q >> 6);
            float gt  = a * s_sh[h*32 + cc] * swv;
            float x1v = (gt - mu) * rs * gam + bet;
            acc += s_x11[c]*x2v + s_x21[c]*x1v;
        }
        s_wt[l] = 1.f / (1.f + expf(-acc));
    }
    __syncthreads();

    const float4* A4 = (const float4*)A;
    float4* O4 = (float4*)(out + (size_t)g * IMG_ELEMS);
    for (int i = tid; i < IMG_ELEMS/4; i += 1024) {
        float sg = s_wt[i >> 3];
        float4 a4 = A4[i];
        float4 o;
        o.x = a4.x*sg;
        o.y = a4.y*sg;
        o.z = a4.z*sg;
        o.w = a4.w*sg;
        O4[i] = o;
    }
}

// ===================== launch =====================
extern "C" void kernel_launch(void* const* d_in, const int* in_sizes, int n_in,
                              void* d_out, int out_size) {
    const float* x     = (const float*)d_in[0];
    const float* w1    = (const float*)d_in[1];
    const float* b1    = (const float*)d_in[2];
    const float* w3    = (const float*)d_in[3];
    const float* b3    = (const float*)d_in[4];
    const float* gamma = (const float*)d_in[5];
    const float* beta  = (const float*)d_in[6];
    float* out = (float*)d_out;

    cudaFuncSetAttribute(k2_conv, cudaFuncAttributeMaxDynamicSharedMemorySize, SM_TOTAL);

    k0_prep<<<1, 256>>>(w3);
    k1_means<<<NIMG, 256>>>(x, w1, b1);
    k2_conv<<<dim3(16, NIMG), 256, SM_TOTAL>>>(x, b3);
    k3_finalize<<<NIMG, 32>>>(beta);
    k4_weights_out<<<NIMG, 1024>>>(x, gamma, beta, out);
}

// round 10
// speedup vs baseline: 1.5940x; 1.1053x over previous
#include <cuda_runtime.h>
#include <cuda_bf16.h>
#include <cstdint>
#include <math.h>

typedef unsigned int u32;

#define NIMG 512
#define IMG_ELEMS (64*64*32)

// ---- scratch (device globals; allocation-free rule) ----
__device__ float g_x2[67108864];        // conv output (+b3)
__device__ float g_sh[NIMG*64*32];
__device__ float g_sw[NIMG*64*32];
__device__ float g_sum[NIMG*32];
__device__ float g_sumsq[NIMG*32];
__device__ float g_colsum[NIMG*32];
__device__ float g_mu[NIMG*32];
__device__ float g_rs[NIMG*32];
__device__ float g_x21[NIMG*32];
__device__ float g_x11[32];
// W transposed [d][k], bf16 hi/lo, row stride 328 bf16 (=656 B; ldmatrix conflict-free)
__device__ __align__(16) unsigned short g_whi[32*328];
__device__ __align__(16) unsigned short g_wlo[32*328];

__device__ __forceinline__ u32 pack_bf(float x, float y) {
    u32 a = (u32)__bfloat16_as_ushort(__float2bfloat16(x));
    u32 b = (u32)__bfloat16_as_ushort(__float2bfloat16(y));
    return a | (b << 16);
}
// m16n8k16 row.col bf16 -> f32 accumulate (HMMA.16816; valid on base sm_103)
__device__ __forceinline__ void mma_bf16(float* c, const u32* a, const u32* b) {
    asm volatile("mma.sync.aligned.m16n8k16.row.col.f32.bf16.bf16.f32 {%0,%1,%2,%3}, {%4,%5,%6,%7}, {%8,%9}, {%0,%1,%2,%3};" : "+f"(c[0]), "+f"(c[1]), "+f"(c[2]), "+f"(c[3]) : "r"(a[0]), "r"(a[1]), "r"(a[2]), "r"(a[3]), "r"(b[0]), "r"(b[1]));
}
__device__ __forceinline__ void ldsm_x4(u32* r, u32 saddr) {
    asm volatile("ldmatrix.sync.aligned.m8n8.x4.shared.b16 {%0,%1,%2,%3}, [%4];" : "=r"(r[0]), "=r"(r[1]), "=r"(r[2]), "=r"(r[3]) : "r"(saddr));
}
__device__ __forceinline__ u32 smem_u32(const void* p) {
    u32 a;
    asm("{ .reg .u64 t; cvta.to.shared.u64 t, %1; cvt.u32.u64 %0, t; }" : "=r"(a) : "l"(p));
    return a;
}

// ===================== K0: transpose + bf16-split conv weights =====================
__global__ void k0_prep(const float* __restrict__ w3) {
    for (int idx = threadIdx.x; idx < 32*328; idx += blockDim.x) {
        int d = idx / 328;
        int k = idx % 328;
        float v = (k < 288) ? w3[k*32 + d] : 0.f;
        __nv_bfloat16 hb = __float2bfloat16(v);
        float lo = v - __bfloat162float(hb);
        g_whi[idx] = __bfloat16_as_ushort(hb);
        g_wlo[idx] = __bfloat16_as_ushort(__float2bfloat16(lo));
    }
}

// ===================== K1: row/col means + 32x32 matmul + sigmoid (+ zero stats) =====================
__global__ void __launch_bounds__(256) k1_means(const float* __restrict__ x,
                                                const float* __restrict__ w1,
                                                const float* __restrict__ b1) {
    int g = blockIdx.x;
    const float* A = x + (size_t)g * IMG_ELEMS;
    __shared__ float s_xh[2048];
    __shared__ float s_xw[2048];
    __shared__ float s_w1[1024];
    int tid = threadIdx.x;
    int lane = tid & 31;
    int wid = tid >> 5;

    if (tid < 32) {
        g_sum[g*32+tid] = 0.f;
        g_sumsq[g*32+tid] = 0.f;
        g_colsum[g*32+tid] = 0.f;
    }
    for (int i = tid; i < 1024; i += 256) s_w1[i] = w1[i];

    for (int h = wid; h < 64; h += 8) {
        float acc = 0.f;
        for (int w = 0; w < 64; w++) acc += A[(h*64 + w)*32 + lane];
        s_xh[h*32 + lane] = acc * (1.f/64.f);
    }
    for (int w = wid; w < 64; w += 8) {
        float acc = 0.f;
        for (int h = 0; h < 64; h++) acc += A[(h*64 + w)*32 + lane];
        s_xw[w*32 + lane] = acc * (1.f/64.f);
    }
    __syncthreads();
    for (int i = tid; i < 4096; i += 256) {
        int row = i >> 5;
        int d = i & 31;
        const float* v = (row < 64) ? (s_xh + row*32) : (s_xw + (row-64)*32);
        float acc = b1[d];
        for (int c = 0; c < 32; c++) acc = fmaf(v[c], s_w1[c*32 + d], acc);
        float s = 1.f / (1.f + expf(-acc));
        if (row < 64) g_sh[(g*64 + row)*32 + d] = s;
        else g_sw[(g*64 + (row-64))*32 + d] = s;
    }
}

// ===================== K2: HMMA bf16-split conv (ldmatrix) + colsum + gated GN stats =====================
// Block: 4 output rows x 64 cols x 32ch. 8 warps; warp = 32-pixel strip (2 m16 tiles x 4 n8 tiles).
// smem: s_out ALIASES the input-hi plane -> 108416 B -> 2 CTAs/SM.
#define SM_WH  0
#define SM_WL  20992
#define SM_INH 41984
#define SM_INL 73664
#define SM_RED 105344
#define SM_TOTAL 108416
// input planes: [6 rows][66 cols][32 ci bf16], col stride 20 u32 (80 B)
#define PLANE_DELTA 31680u
#define WDELTA 20992u

__global__ void __launch_bounds__(256, 2) k2_conv(const float* __restrict__ x,
                                                  const float* __restrict__ b3) {
    int gimg = blockIdx.y;
    int h0 = blockIdx.x * 4;
    const float* A = x + (size_t)gimg * IMG_ELEMS;
    extern __shared__ char sm[];
    u32 smb = smem_u32(sm);
    u32* inh32 = (u32*)(sm + SM_INH);
    u32* inl32 = (u32*)(sm + SM_INL);
    float* s_out = (float*)(sm + SM_INH);   // alias: valid only after all input reads
    float* s_red = (float*)(sm + SM_RED);
    int tid = threadIdx.x;
    int lane = tid & 31;
    int wid = tid >> 5;

    // load W planes (pre-split/transposed): 2 x 20992 B
    {
        const float4* srcH = (const float4*)g_whi;
        const float4* srcL = (const float4*)g_wlo;
        float4* dstH = (float4*)(sm + SM_WH);
        float4* dstL = (float4*)(sm + SM_WL);
        for (int i = tid; i < 1312; i += 256) {
            dstH[i] = srcH[i];
            dstL[i] = srcL[i];
        }
    }
    // fill halo input tile (rows h0-1 .. h0+4), bf16 hi/lo planes
    for (int i = tid; i < (6*66*32)/4; i += 256) {
        int idx = i * 4;
        int r = idx / 2112;
        int rem = idx - r*2112;
        int col = rem >> 5;
        int ci = rem & 31;
        int h = h0 - 1 + r;
        float4 v = make_float4(0.f, 0.f, 0.f, 0.f);
        if (col >= 1 && col <= 64 && h >= 0 && h < 64)
            v = *(const float4*)(A + (h*64 + col - 1)*32 + ci);
        __nv_bfloat16 h0b = __float2bfloat16(v.x);
        __nv_bfloat16 h1b = __float2bfloat16(v.y);
        __nv_bfloat16 h2b = __float2bfloat16(v.z);
        __nv_bfloat16 h3b = __float2bfloat16(v.w);
        float l0 = v.x - __bfloat162float(h0b);
        float l1 = v.y - __bfloat162float(h1b);
        float l2 = v.z - __bfloat162float(h2b);
        float l3 = v.w - __bfloat162float(h3b);
        int wbase = (r*66 + col)*20 + (ci >> 1);
        inh32[wbase]     = ((u32)__bfloat16_as_ushort(h0b)) | (((u32)__bfloat16_as_ushort(h1b)) << 16);
        inh32[wbase + 1] = ((u32)__bfloat16_as_ushort(h2b)) | (((u32)__bfloat16_as_ushort(h3b)) << 16);
        inl32[wbase]     = pack_bf(l0, l1);
        inl32[wbase + 1] = pack_bf(l2, l3);
    }
    __syncthreads();

    int hl = wid >> 1;            // output row within tile (0..3)
    int wbase = (wid & 1) * 32;   // col base of this warp's 32-pixel strip
    int g = lane >> 2;            // fragment group (for epilogue mapping)
    int t = lane & 3;

    // lane-constant ldmatrix address components
    const u32 inh_a = smb + SM_INH;
    const u32 wh_a  = smb + SM_WH;
    const u32 alane = (u32)((lane & 15) * 80 + (lane >> 4) * 16);
    const u32 blane = (u32)(((lane >> 4) * 8 + (lane & 7)) * 656 + ((lane >> 3) & 1) * 16);

    float acc[2][4][4];
    for (int m = 0; m < 2; m++)
        for (int n = 0; n < 4; n++)
            for (int r = 0; r < 4; r++) acc[m][n][r] = 0.f;

    for (int tap = 0; tap < 9; tap++) {
        int kh = tap / 3;
        int kw = tap - kh*3;
        u32 apix = inh_a + (u32)(((hl + kh)*66 + wbase + kw) * 80) + alane;
        u32 wtap = wh_a + blane + (u32)(tap * 64);
        #pragma unroll
        for (int c = 0; c < 2; c++) {
            u32 aoff = apix + (u32)(c * 32);
            u32 boff = wtap + (u32)(c * 32);
            u32 ah0[4], ah1[4], al0[4], al1[4];
            ldsm_x4(ah0, aoff);
            ldsm_x4(ah1, aoff + 1280u);
            ldsm_x4(al0, aoff + PLANE_DELTA);
            ldsm_x4(al1, aoff + PLANE_DELTA + 1280u);
            u32 bh[2][4], bl[2][4];
            ldsm_x4(bh[0], boff);
            ldsm_x4(bh[1], boff + 10496u);          // +16 rows * 656 B
            ldsm_x4(bl[0], boff + WDELTA);
            ldsm_x4(bl[1], boff + WDELTA + 10496u);
            #pragma unroll
            for (int n = 0; n < 4; n++) {
                const u32* Bh = &bh[n >> 1][(n & 1) * 2];
                const u32* Bl = &bl[n >> 1][(n & 1) * 2];
                mma_bf16(acc[0][n], ah0, Bh);
                mma_bf16(acc[0][n], al0, Bh);
                mma_bf16(acc[0][n], ah0, Bl);
                mma_bf16(acc[1][n], ah1, Bh);
                mma_bf16(acc[1][n], al1, Bh);
                mma_bf16(acc[1][n], ah1, Bl);
            }
        }
    }

    // gated GN stats FIRST (reads input planes; lane = channel)
    int hglob = h0 + hl;
    float shv = g_sh[(gimg*64 + hglob)*32 + lane];
    const __nv_bfloat16* inh16 = (const __nv_bfloat16*)(sm + SM_INH);
    const __nv_bfloat16* inl16 = (const __nv_bfloat16*)(sm + SM_INL);
    float s1 = 0.f, s2 = 0.f;
    for (int j2 = 0; j2 < 32; j2++) {
        int wq = wbase + j2;
        int i16 = ((hl + 1)*66 + wq + 1)*40 + lane;
        float a = __bfloat162float(inh16[i16]) + __bfloat162float(inl16[i16]);
        float gt = a * shv * g_sw[(gimg*64 + wq)*32 + lane];
        s1 += gt;
        s2 += gt*gt;
    }
    // all input reads done across ALL warps before s_out (alias) is written
    __syncthreads();

    // stage D to smem: s_out[pix_in_tile * 34 + ch]
    #pragma unroll
    for (int m = 0; m < 2; m++) {
        #pragma unroll
        for (int n = 0; n < 4; n++) {
            int pix0 = hl*64 + wbase + m*16 + g;
            int ch = n*8 + 2*t;
            s_out[pix0*34 + ch]       = acc[m][n][0];
            s_out[pix0*34 + ch + 1]   = acc[m][n][1];
            s_out[(pix0+8)*34 + ch]   = acc[m][n][2];
            s_out[(pix0+8)*34 + ch+1] = acc[m][n][3];
        }
    }
    __syncwarp();   // staging is warp-local

    // coalesced x2 write (+b3) + channel sums (lane = channel)
    float b3v = b3[lane];
    float csum = 0.f;
    for (int j2 = 0; j2 < 32; j2++) {
        int pix = hl*64 + wbase + j2;
        float v = s_out[pix*34 + lane] + b3v;
        g_x2[((size_t)gimg*4096 + (size_t)hglob*64 + wbase + j2)*32 + lane] = v;
        csum += v;
    }

    s_red[(0*8 + wid)*32 + lane] = csum;
    s_red[(1*8 + wid)*32 + lane] = s1;
    s_red[(2*8 + wid)*32 + lane] = s2;
    __syncthreads();
    if (wid < 3) {
        float tsum = 0.f;
        for (int k = 0; k < 8; k++) tsum += s_red[(wid*8 + k)*32 + lane];
        float* dst = (wid == 0) ? g_colsum : (wid == 1) ? g_sum : g_sumsq;
        atomicAdd(dst + gimg*32 + lane, tsum);
    }
}

// ===================== K3: mu/rsqrt, softmax(x21), softmax(gn_beta)=x11 =====================
__global__ void k3_finalize(const float* __restrict__ gn_beta) {
    int g = blockIdx.x;
    int t = threadIdx.x;
    float mu  = g_sum[g*32 + t] * (1.f/4096.f);
    float var = g_sumsq[g*32 + t] * (1.f/4096.f) - mu*mu;
    g_mu[g*32 + t] = mu;
    g_rs[g*32 + t] = rsqrtf(var + 1e-3f);

    float m = g_colsum[g*32 + t] * (1.f/4096.f);
    float mx = m;
    for (int o = 16; o > 0; o >>= 1) mx = fmaxf(mx, __shfl_xor_sync(0xffffffffu, mx, o));
    float e = expf(m - mx);
    float se = e;
    for (int o = 16; o > 0; o >>= 1) se += __shfl_xor_sync(0xffffffffu, se, o);
    g_x21[g*32 + t] = e / se;

    if (g == 0) {
        float bb = gn_beta[t];
        float mx2 = bb;
        for (int o = 16; o > 0; o >>= 1) mx2 = fmaxf(mx2, __shfl_xor_sync(0xffffffffu, mx2, o));
        float e2 = expf(bb - mx2);
        float s2 = e2;
        for (int o = 16; o > 0; o >>= 1) s2 += __shfl_xor_sync(0xffffffffu, s2, o);
        g_x11[t] = e2 / s2;
    }
}

// ===================== K4: weights (flat einsum) + sigmoid + output =====================
__global__ void __launch_bounds__(1024) k4_weights_out(const float* __restrict__ x,
                                                       const float* __restrict__ gn_gamma,
                                                       const float* __restrict__ gn_beta,
                                                       float* __restrict__ out) {
    int g = blockIdx.x;
    int tid = threadIdx.x;
    const float* A  = x    + (size_t)g * IMG_ELEMS;
    const float* X2 = g_x2 + (size_t)g * IMG_ELEMS;
    __shared__ float s_wt[4096];
    __shared__ float s_sh[2048];
    __shared__ float s_sw[2048];
    __shared__ float s_x11[32];
    __shared__ float s_x21[32];
    __shared__ float s_mu[32];
    __shared__ float s_rs[32];
    __shared__ float s_gb[64];
    for (int i = tid; i < 2048; i += 1024) {
        s_sh[i] = g_sh[g*2048 + i];
        s_sw[i] = g_sw[g*2048 + i];
    }
    if (tid < 32) {
        s_x11[tid] = g_x11[tid];
        s_x21[tid] = g_x21[g*32 + tid];
        s_mu[tid]  = g_mu[g*32 + tid];
        s_rs[tid]  = g_rs[g*32 + tid];
        s_gb[tid]      = gn_gamma[tid];
        s_gb[32 + tid] = gn_beta[tid];
    }
    __syncthreads();

    for (int k = 0; k < 4; k++) {
        int l  = tid + k*1024;
        int cc = l & 31;
        int q  = l >> 5;
        int w  = q & 63;
        float rs = s_rs[cc];
        float mu = s_mu[cc];
        float gam = s_gb[cc];
        float bet = s_gb[32 + cc];
        float swv = s_sw[w*32 + cc];
        float acc = 0.f;
        for (int c = 0; c < 32; c++) {
            int f = c*4096 + l;
            float x2v = X2[f];
            float a   = A[f];
            int h = 2*c + (q >> 6);
            float gt  = a * s_sh[h*32 + cc] * swv;
            float x1v = (gt - mu) * rs * gam + bet;
            acc += s_x11[c]*x2v + s_x21[c]*x1v;
        }
        s_wt[l] = 1.f / (1.f + expf(-acc));
    }
    __syncthreads();

    const float4* A4 = (const float4*)A;
    float4* O4 = (float4*)(out + (size_t)g * IMG_ELEMS);
    for (int i = tid; i < IMG_ELEMS/4; i += 1024) {
        float sg = s_wt[i >> 3];
        float4 a4 = A4[i];
        float4 o;
        o.x = a4.x*sg;
        o.y = a4.y*sg;
        o.z = a4.z*sg;
        o.w = a4.w*sg;
        O4[i] = o;
    }
}

// ===================== launch =====================
extern "C" void kernel_launch(void* const* d_in, const int* in_sizes, int n_in,
                              void* d_out, int out_size) {
    const float* x     = (const float*)d_in[0];
    const float* w1    = (const float*)d_in[1];
    const float* b1    = (const float*)d_in[2];
    const float* w3    = (const float*)d_in[3];
    const float* b3    = (const float*)d_in[4];
    const float* gamma = (const float*)d_in[5];
    const float* beta  = (const float*)d_in[6];
    float* out = (float*)d_out;

    cudaFuncSetAttribute(k2_conv, cudaFuncAttributeMaxDynamicSharedMemorySize, SM_TOTAL);

    k0_prep<<<1, 256>>>(w3);
    k1_means<<<NIMG, 256>>>(x, w1, b1);
    k2_conv<<<dim3(16, NIMG), 256, SM_TOTAL>>>(x, b3);
    k3_finalize<<<NIMG, 32>>>(beta);
    k4_weights_out<<<NIMG, 1024>>>(x, gamma, beta, out);
}

// round 11
// speedup vs baseline: 1.9130x; 1.2001x over previous
#include <cuda_runtime.h>
#include <cuda_fp16.h>
#include <cstdint>
#include <math.h>

typedef unsigned int u32;

#define NIMG 512
#define IMG_ELEMS (64*64*32)

// ---- scratch (device globals; allocation-free rule) ----
__device__ float g_x2[67108864];        // conv output (+b3)
__device__ float g_sh[NIMG*64*32];
__device__ float g_sw[NIMG*64*32];
__device__ float g_sum[NIMG*32];
__device__ float g_sumsq[NIMG*32];
__device__ float g_colsum[NIMG*32];
__device__ float g_mu[NIMG*32];
__device__ float g_rs[NIMG*32];
__device__ float g_x21[NIMG*32];
__device__ float g_x11[32];
// W transposed [d][k], fp16, row stride 328 halves (=656 B; ldmatrix conflict-free)
__device__ __align__(16) unsigned short g_whi[32*328];

__device__ __forceinline__ u32 pack_h2(float x, float y) {
    __half2 h = __floats2half2_rn(x, y);
    return *(u32*)&h;
}
// m16n8k16 row.col fp16 -> f32 accumulate (HMMA.16816; valid on base sm_103)
__device__ __forceinline__ void mma_f16(float* c, const u32* a, const u32* b) {
    asm volatile("mma.sync.aligned.m16n8k16.row.col.f32.f16.f16.f32 {%0,%1,%2,%3}, {%4,%5,%6,%7}, {%8,%9}, {%0,%1,%2,%3};" : "+f"(c[0]), "+f"(c[1]), "+f"(c[2]), "+f"(c[3]) : "r"(a[0]), "r"(a[1]), "r"(a[2]), "r"(a[3]), "r"(b[0]), "r"(b[1]));
}
__device__ __forceinline__ void ldsm_x4(u32* r, u32 saddr) {
    asm volatile("ldmatrix.sync.aligned.m8n8.x4.shared.b16 {%0,%1,%2,%3}, [%4];" : "=r"(r[0]), "=r"(r[1]), "=r"(r[2]), "=r"(r[3]) : "r"(saddr));
}
__device__ __forceinline__ u32 smem_u32(const void* p) {
    u32 a;
    asm("{ .reg .u64 t; cvta.to.shared.u64 t, %1; cvt.u32.u64 %0, t; }" : "=r"(a) : "l"(p));
    return a;
}

// ===================== K0: transpose conv weights to fp16 =====================
__global__ void k0_prep(const float* __restrict__ w3) {
    for (int idx = threadIdx.x; idx < 32*328; idx += blockDim.x) {
        int d = idx / 328;
        int k = idx % 328;
        float v = (k < 288) ? w3[k*32 + d] : 0.f;
        __half hb = __float2half_rn(v);
        g_whi[idx] = *(unsigned short*)&hb;
    }
}

// ===================== K1: row/col means + 32x32 matmul + sigmoid (+ zero stats) =====================
__global__ void __launch_bounds__(256) k1_means(const float* __restrict__ x,
                                                const float* __restrict__ w1,
                                                const float* __restrict__ b1) {
    int g = blockIdx.x;
    const float* A = x + (size_t)g * IMG_ELEMS;
    __shared__ float s_xh[2048];
    __shared__ float s_xw[2048];
    __shared__ float s_w1[1024];
    int tid = threadIdx.x;
    int lane = tid & 31;
    int wid = tid >> 5;

    if (tid < 32) {
        g_sum[g*32+tid] = 0.f;
        g_sumsq[g*32+tid] = 0.f;
        g_colsum[g*32+tid] = 0.f;
    }
    for (int i = tid; i < 1024; i += 256) s_w1[i] = w1[i];

    for (int h = wid; h < 64; h += 8) {
        float acc = 0.f;
        for (int w = 0; w < 64; w++) acc += A[(h*64 + w)*32 + lane];
        s_xh[h*32 + lane] = acc * (1.f/64.f);
    }
    for (int w = wid; w < 64; w += 8) {
        float acc = 0.f;
        for (int h = 0; h < 64; h++) acc += A[(h*64 + w)*32 + lane];
        s_xw[w*32 + lane] = acc * (1.f/64.f);
    }
    __syncthreads();
    for (int i = tid; i < 4096; i += 256) {
        int row = i >> 5;
        int d = i & 31;
        const float* v = (row < 64) ? (s_xh + row*32) : (s_xw + (row-64)*32);
        float acc = b1[d];
        for (int c = 0; c < 32; c++) acc = fmaf(v[c], s_w1[c*32 + d], acc);
        float s = 1.f / (1.f + expf(-acc));
        if (row < 64) g_sh[(g*64 + row)*32 + d] = s;
        else g_sw[(g*64 + (row-64))*32 + d] = s;
    }
}

// ===================== K2: single-term fp16 HMMA conv + colsum + gated GN stats =====================
// Block: 4 output rows x 64 cols x 32ch. 8 warps; warp = 32-pixel strip (2 m16 tiles x 4 n8 tiles).
// MMA uses fp16-hi plane only (err ~2^-12); GN stats use hi+lo (err ~2^-24).
#define SM_WH  0
#define SM_INH 20992
#define SM_INL 52672
#define SM_RED 84352
#define SM_TOTAL 87424
// input planes: [6 rows][66 cols][32 ci fp16], col stride 20 u32 (80 B)
#define PLANE_DELTA 31680u

__global__ void __launch_bounds__(256, 2) k2_conv(const float* __restrict__ x,
                                                  const float* __restrict__ b3) {
    int gimg = blockIdx.y;
    int h0 = blockIdx.x * 4;
    const float* A = x + (size_t)gimg * IMG_ELEMS;
    extern __shared__ char sm[];
    u32 smb = smem_u32(sm);
    u32* inh32 = (u32*)(sm + SM_INH);
    u32* inl32 = (u32*)(sm + SM_INL);
    float* s_out = (float*)(sm + SM_INH);   // alias: valid only after all input reads
    float* s_red = (float*)(sm + SM_RED);
    int tid = threadIdx.x;
    int lane = tid & 31;
    int wid = tid >> 5;

    // load W plane (pre-transposed fp16): 20992 B
    {
        const float4* srcH = (const float4*)g_whi;
        float4* dstH = (float4*)(sm + SM_WH);
        for (int i = tid; i < 1312; i += 256) dstH[i] = srcH[i];
    }
    // fill halo input tile (rows h0-1 .. h0+4), fp16 hi/lo planes
    for (int i = tid; i < (6*66*32)/4; i += 256) {
        int idx = i * 4;
        int r = idx / 2112;
        int rem = idx - r*2112;
        int col = rem >> 5;
        int ci = rem & 31;
        int h = h0 - 1 + r;
        float4 v = make_float4(0.f, 0.f, 0.f, 0.f);
        if (col >= 1 && col <= 64 && h >= 0 && h < 64)
            v = *(const float4*)(A + (h*64 + col - 1)*32 + ci);
        __half h0b = __float2half_rn(v.x);
        __half h1b = __float2half_rn(v.y);
        __half h2b = __float2half_rn(v.z);
        __half h3b = __float2half_rn(v.w);
        float l0 = v.x - __half2float(h0b);
        float l1 = v.y - __half2float(h1b);
        float l2 = v.z - __half2float(h2b);
        float l3 = v.w - __half2float(h3b);
        int wbase = (r*66 + col)*20 + (ci >> 1);
        inh32[wbase]     = ((u32)*(unsigned short*)&h0b) | (((u32)*(unsigned short*)&h1b) << 16);
        inh32[wbase + 1] = ((u32)*(unsigned short*)&h2b) | (((u32)*(unsigned short*)&h3b) << 16);
        inl32[wbase]     = pack_h2(l0, l1);
        inl32[wbase + 1] = pack_h2(l2, l3);
    }
    __syncthreads();

    int hl = wid >> 1;            // output row within tile (0..3)
    int wbase = (wid & 1) * 32;   // col base of this warp's 32-pixel strip
    int g = lane >> 2;            // fragment group (for epilogue mapping)
    int t = lane & 3;

    // lane-constant ldmatrix address components
    const u32 inh_a = smb + SM_INH;
    const u32 wh_a  = smb + SM_WH;
    const u32 alane = (u32)((lane & 15) * 80 + (lane >> 4) * 16);
    const u32 blane = (u32)(((lane >> 4) * 8 + (lane & 7)) * 656 + ((lane >> 3) & 1) * 16);

    float acc[2][4][4];
    for (int m = 0; m < 2; m++)
        for (int n = 0; n < 4; n++)
            for (int r = 0; r < 4; r++) acc[m][n][r] = 0.f;

    for (int tap = 0; tap < 9; tap++) {
        int kh = tap / 3;
        int kw = tap - kh*3;
        u32 apix = inh_a + (u32)(((hl + kh)*66 + wbase + kw) * 80) + alane;
        u32 wtap = wh_a + blane + (u32)(tap * 64);
        #pragma unroll
        for (int c = 0; c < 2; c++) {
            u32 aoff = apix + (u32)(c * 32);
            u32 boff = wtap + (u32)(c * 32);
            u32 ah0[4], ah1[4];
            ldsm_x4(ah0, aoff);
            ldsm_x4(ah1, aoff + 1280u);
            u32 bh[2][4];
            ldsm_x4(bh[0], boff);
            ldsm_x4(bh[1], boff + 10496u);          // +16 rows * 656 B
            #pragma unroll
            for (int n = 0; n < 4; n++) {
                const u32* Bh = &bh[n >> 1][(n & 1) * 2];
                mma_f16(acc[0][n], ah0, Bh);
                mma_f16(acc[1][n], ah1, Bh);
            }
        }
    }

    // gated GN stats FIRST (reads input planes hi+lo; lane = channel)
    int hglob = h0 + hl;
    float shv = g_sh[(gimg*64 + hglob)*32 + lane];
    const __half* inh16 = (const __half*)(sm + SM_INH);
    const __half* inl16 = (const __half*)(sm + SM_INL);
    float s1 = 0.f, s2 = 0.f;
    for (int j2 = 0; j2 < 32; j2++) {
        int wq = wbase + j2;
        int i16 = ((hl + 1)*66 + wq + 1)*40 + lane;
        float a = __half2float(inh16[i16]) + __half2float(inl16[i16]);
        float gt = a * shv * g_sw[(gimg*64 + wq)*32 + lane];
        s1 += gt;
        s2 += gt*gt;
    }
    // all input reads done across ALL warps before s_out (alias) is written
    __syncthreads();

    // stage D to smem: s_out[pix_in_tile * 34 + ch]
    #pragma unroll
    for (int m = 0; m < 2; m++) {
        #pragma unroll
        for (int n = 0; n < 4; n++) {
            int pix0 = hl*64 + wbase + m*16 + g;
            int ch = n*8 + 2*t;
            s_out[pix0*34 + ch]       = acc[m][n][0];
            s_out[pix0*34 + ch + 1]   = acc[m][n][1];
            s_out[(pix0+8)*34 + ch]   = acc[m][n][2];
            s_out[(pix0+8)*34 + ch+1] = acc[m][n][3];
        }
    }
    __syncwarp();   // staging is warp-local

    // coalesced x2 write (+b3) + channel sums (lane = channel)
    float b3v = b3[lane];
    float csum = 0.f;
    for (int j2 = 0; j2 < 32; j2++) {
        int pix = hl*64 + wbase + j2;
        float v = s_out[pix*34 + lane] + b3v;
        g_x2[((size_t)gimg*4096 + (size_t)hglob*64 + wbase + j2)*32 + lane] = v;
        csum += v;
    }

    s_red[(0*8 + wid)*32 + lane] = csum;
    s_red[(1*8 + wid)*32 + lane] = s1;
    s_red[(2*8 + wid)*32 + lane] = s2;
    __syncthreads();
    if (wid < 3) {
        float tsum = 0.f;
        for (int k = 0; k < 8; k++) tsum += s_red[(wid*8 + k)*32 + lane];
        float* dst = (wid == 0) ? g_colsum : (wid == 1) ? g_sum : g_sumsq;
        atomicAdd(dst + gimg*32 + lane, tsum);
    }
}

// ===================== K3: mu/rsqrt, softmax(x21), softmax(gn_beta)=x11 =====================
__global__ void k3_finalize(const float* __restrict__ gn_beta) {
    int g = blockIdx.x;
    int t = threadIdx.x;
    float mu  = g_sum[g*32 + t] * (1.f/4096.f);
    float var = g_sumsq[g*32 + t] * (1.f/4096.f) - mu*mu;
    g_mu[g*32 + t] = mu;
    g_rs[g*32 + t] = rsqrtf(var + 1e-3f);

    float m = g_colsum[g*32 + t] * (1.f/4096.f);
    float mx = m;
    for (int o = 16; o > 0; o >>= 1) mx = fmaxf(mx, __shfl_xor_sync(0xffffffffu, mx, o));
    float e = expf(m - mx);
    float se = e;
    for (int o = 16; o > 0; o >>= 1) se += __shfl_xor_sync(0xffffffffu, se, o);
    g_x21[g*32 + t] = e / se;

    if (g == 0) {
        float bb = gn_beta[t];
        float mx2 = bb;
        for (int o = 16; o > 0; o >>= 1) mx2 = fmaxf(mx2, __shfl_xor_sync(0xffffffffu, mx2, o));
        float e2 = expf(bb - mx2);
        float s2 = e2;
        for (int o = 16; o > 0; o >>= 1) s2 += __shfl_xor_sync(0xffffffffu, s2, o);
        g_x11[t] = e2 / s2;
    }
}

// ===================== K4: weights (flat einsum) + sigmoid + output =====================
__global__ void __launch_bounds__(1024) k4_weights_out(const float* __restrict__ x,
                                                       const float* __restrict__ gn_gamma,
                                                       const float* __restrict__ gn_beta,
                                                       float* __restrict__ out) {
    int g = blockIdx.x;
    int tid = threadIdx.x;
    const float* A  = x    + (size_t)g * IMG_ELEMS;
    const float* X2 = g_x2 + (size_t)g * IMG_ELEMS;
    __shared__ float s_wt[4096];
    __shared__ float s_sh[2048];
    __shared__ float s_sw[2048];
    __shared__ float s_x11[32];
    __shared__ float s_x21[32];
    __shared__ float s_mu[32];
    __shared__ float s_rs[32];
    __shared__ float s_gb[64];
    for (int i = tid; i < 2048; i += 1024) {
        s_sh[i] = g_sh[g*2048 + i];
        s_sw[i] = g_sw[g*2048 + i];
    }
    if (tid < 32) {
        s_x11[tid] = g_x11[tid];
        s_x21[tid] = g_x21[g*32 + tid];
        s_mu[tid]  = g_mu[g*32 + tid];
        s_rs[tid]  = g_rs[g*32 + tid];
        s_gb[tid]      = gn_gamma[tid];
        s_gb[32 + tid] = gn_beta[tid];
    }
    __syncthreads();

    for (int k = 0; k < 4; k++) {
        int l  = tid + k*1024;
        int cc = l & 31;
        int q  = l >> 5;
        int w  = q & 63;
        float rs = s_rs[cc];
        float mu = s_mu[cc];
        float gam = s_gb[cc];
        float bet = s_gb[32 + cc];
        float swv = s_sw[w*32 + cc];
        float acc = 0.f;
        for (int c = 0; c < 32; c++) {
            int f = c*4096 + l;
            float x2v = X2[f];
            float a   = A[f];
            int h = 2*c + (q >> 6);
            float gt  = a * s_sh[h*32 + cc] * swv;
            float x1v = (gt - mu) * rs * gam + bet;
            acc += s_x11[c]*x2v + s_x21[c]*x1v;
        }
        s_wt[l] = 1.f / (1.f + expf(-acc));
    }
    __syncthreads();

    const float4* A4 = (const float4*)A;
    float4* O4 = (float4*)(out + (size_t)g * IMG_ELEMS);
    for (int i = tid; i < IMG_ELEMS/4; i += 1024) {
        float sg = s_wt[i >> 3];
        float4 a4 = A4[i];
        float4 o;
        o.x = a4.x*sg;
        o.y = a4.y*sg;
        o.z = a4.z*sg;
        o.w = a4.w*sg;
        O4[i] = o;
    }
}

// ===================== launch =====================
extern "C" void kernel_launch(void* const* d_in, const int* in_sizes, int n_in,
                              void* d_out, int out_size) {
    const float* x     = (const float*)d_in[0];
    const float* w1    = (const float*)d_in[1];
    const float* b1    = (const float*)d_in[2];
    const float* w3    = (const float*)d_in[3];
    const float* b3    = (const float*)d_in[4];
    const float* gamma = (const float*)d_in[5];
    const float* beta  = (const float*)d_in[6];
    float* out = (float*)d_out;

    cudaFuncSetAttribute(k2_conv, cudaFuncAttributeMaxDynamicSharedMemorySize, SM_TOTAL);

    k0_prep<<<1, 256>>>(w3);
    k1_means<<<NIMG, 256>>>(x, w1, b1);
    k2_conv<<<dim3(16, NIMG), 256, SM_TOTAL>>>(x, b3);
    k3_finalize<<<NIMG, 32>>>(beta);
    k4_weights_out<<<NIMG, 1024>>>(x, gamma, beta, out);
}

// round 13
// speedup vs baseline: 2.2323x; 1.1669x over previous
#include <cuda_runtime.h>
#include <cuda_fp16.h>
#include <cstdint>
#include <math.h>

typedef unsigned int u32;

#define NIMG 512
#define IMG_ELEMS (64*64*32)

// ---- scratch (device globals; allocation-free rule) ----
__device__ __half g_x2h[67108864];      // conv output (+b3), fp16
__device__ float g_sh[NIMG*64*32];
__device__ float g_sw[NIMG*64*32];
__device__ float g_sum[NIMG*32];
__device__ float g_sumsq[NIMG*32];
__device__ float g_colsum[NIMG*32];
__device__ float g_mu[NIMG*32];
__device__ float g_rs[NIMG*32];
__device__ float g_x21[NIMG*32];
__device__ float g_x11[32];
// W transposed [d][k], fp16, row stride 328 halves (=656 B; ldmatrix conflict-free)
__device__ __align__(16) unsigned short g_whi[32*328];

// m16n8k16 row.col fp16 -> f32 accumulate (HMMA.16816; valid on base sm_103)
__device__ __forceinline__ void mma_f16(float* c, const u32* a, const u32* b) {
    asm volatile("mma.sync.aligned.m16n8k16.row.col.f32.f16.f16.f32 {%0,%1,%2,%3}, {%4,%5,%6,%7}, {%8,%9}, {%0,%1,%2,%3};" : "+f"(c[0]), "+f"(c[1]), "+f"(c[2]), "+f"(c[3]) : "r"(a[0]), "r"(a[1]), "r"(a[2]), "r"(a[3]), "r"(b[0]), "r"(b[1]));
}
__device__ __forceinline__ void ldsm_x4(u32* r, u32 saddr) {
    asm volatile("ldmatrix.sync.aligned.m8n8.x4.shared.b16 {%0,%1,%2,%3}, [%4];" : "=r"(r[0]), "=r"(r[1]), "=r"(r[2]), "=r"(r[3]) : "r"(saddr));
}
__device__ __forceinline__ u32 smem_u32(const void* p) {
    u32 a;
    asm("{ .reg .u64 t; cvta.to.shared.u64 t, %1; cvt.u32.u64 %0, t; }" : "=r"(a) : "l"(p));
    return a;
}

// ===================== K0: transpose conv weights to fp16 =====================
__global__ void k0_prep(const float* __restrict__ w3) {
    for (int idx = threadIdx.x; idx < 32*328; idx += blockDim.x) {
        int d = idx / 328;
        int k = idx % 328;
        float v = (k < 288) ? w3[k*32 + d] : 0.f;
        __half hb = __float2half_rn(v);
        g_whi[idx] = *(unsigned short*)&hb;
    }
}

// ===================== K1: row/col means + 32x32 matmul + sigmoid (+ zero stats) =====================
__global__ void __launch_bounds__(256) k1_means(const float* __restrict__ x,
                                                const float* __restrict__ w1,
                                                const float* __restrict__ b1) {
    int g = blockIdx.x;
    const float* A = x + (size_t)g * IMG_ELEMS;
    __shared__ float s_xh[2048];
    __shared__ float s_xw[2048];
    __shared__ float s_w1[1024];
    int tid = threadIdx.x;
    int lane = tid & 31;
    int wid = tid >> 5;

    if (tid < 32) {
        g_sum[g*32+tid] = 0.f;
        g_sumsq[g*32+tid] = 0.f;
        g_colsum[g*32+tid] = 0.f;
    }
    for (int i = tid; i < 1024; i += 256) s_w1[i] = w1[i];

    for (int h = wid; h < 64; h += 8) {
        float acc = 0.f;
        for (int w = 0; w < 64; w++) acc += A[(h*64 + w)*32 + lane];
        s_xh[h*32 + lane] = acc * (1.f/64.f);
    }
    for (int w = wid; w < 64; w += 8) {
        float acc = 0.f;
        for (int h = 0; h < 64; h++) acc += A[(h*64 + w)*32 + lane];
        s_xw[w*32 + lane] = acc * (1.f/64.f);
    }
    __syncthreads();
    for (int i = tid; i < 4096; i += 256) {
        int row = i >> 5;
        int d = i & 31;
        const float* v = (row < 64) ? (s_xh + row*32) : (s_xw + (row-64)*32);
        float acc = b1[d];
        for (int c = 0; c < 32; c++) acc = fmaf(v[c], s_w1[c*32 + d], acc);
        float s = 1.f / (1.f + expf(-acc));
        if (row < 64) g_sh[(g*64 + row)*32 + d] = s;
        else g_sw[(g*64 + (row-64))*32 + d] = s;
    }
}

// ===================== K2: fp16 HMMA conv, stats fused into fill =====================
// Block: 4 output rows x 64 cols x 32ch. 8 warps; warp = 32-pixel strip.
// GN stats computed from fp32 during fill (no lo plane). x2 stored fp16.
// smem: input plane 31680 B at SM_INH; s_out alias needs 34816 B, so SM_RED
// sits past SM_INH+34816 (R12 bug: s_out overran SM_TOTAL).
#define SM_WH  0
#define SM_INH 20992
#define SM_RED 55808
#define SM_GN  56832
#define SM_TOTAL 57344
// input plane: [6 rows][66 cols][32 ci fp16], col stride 20 u32 (80 B)

__global__ void __launch_bounds__(256, 3) k2_conv(const float* __restrict__ x,
                                                  const float* __restrict__ b3) {
    int gimg = blockIdx.y;
    int h0 = blockIdx.x * 4;
    const float* A = x + (size_t)gimg * IMG_ELEMS;
    extern __shared__ char sm[];
    u32 smb = smem_u32(sm);
    u32* inh32 = (u32*)(sm + SM_INH);
    float* s_out = (float*)(sm + SM_INH);   // alias: valid only after all input reads; 34816 B
    float* s_red = (float*)(sm + SM_RED);
    float* s_gn  = (float*)(sm + SM_GN);    // [0..31] sum, [32..63] sumsq
    int tid = threadIdx.x;
    int lane = tid & 31;
    int wid = tid >> 5;

    if (tid < 64) s_gn[tid] = 0.f;
    // load W plane (pre-transposed fp16): 20992 B
    {
        const float4* srcH = (const float4*)g_whi;
        float4* dstH = (float4*)(sm + SM_WH);
        for (int i = tid; i < 1312; i += 256) dstH[i] = srcH[i];
    }

    // fill halo input tile (rows h0-1 .. h0+4) fp16; gated GN stats from fp32 inline.
    // per-thread ci base is loop-invariant: ci = (tid*4)&31
    float s1v[4] = {0.f, 0.f, 0.f, 0.f};
    float s2v[4] = {0.f, 0.f, 0.f, 0.f};
    for (int i = tid; i < 3168; i += 256) {
        int idx = i * 4;
        int r = idx / 2112;
        int rem = idx - r*2112;
        int col = rem >> 5;
        int ci = rem & 31;
        int h = h0 - 1 + r;
        bool inb = (col >= 1 && col <= 64 && h >= 0 && h < 64);
        float4 v = make_float4(0.f, 0.f, 0.f, 0.f);
        if (inb) v = *(const float4*)(A + (h*64 + col - 1)*32 + ci);
        __half2 p01 = __floats2half2_rn(v.x, v.y);
        __half2 p23 = __floats2half2_rn(v.z, v.w);
        int wb = (r*66 + col)*20 + (ci >> 1);
        inh32[wb]     = *(u32*)&p01;
        inh32[wb + 1] = *(u32*)&p23;
        if (inb && r >= 1 && r <= 4) {
            float4 shv = *(const float4*)(g_sh + (gimg*64 + h)*32 + ci);
            float4 swv = *(const float4*)(g_sw + (gimg*64 + col - 1)*32 + ci);
            float g0 = v.x * shv.x * swv.x;
            float g1 = v.y * shv.y * swv.y;
            float g2 = v.z * shv.z * swv.z;
            float g3 = v.w * shv.w * swv.w;
            s1v[0] += g0; s2v[0] += g0*g0;
            s1v[1] += g1; s2v[1] += g1*g1;
            s1v[2] += g2; s2v[2] += g2*g2;
            s1v[3] += g3; s2v[3] += g3*g3;
        }
    }
    __syncthreads();

    // reduce gated stats: lanes {l, l+8, l+16, l+24} share the same ci base
    #pragma unroll
    for (int j = 0; j < 4; j++) {
        s1v[j] += __shfl_xor_sync(0xffffffffu, s1v[j], 8);
        s1v[j] += __shfl_xor_sync(0xffffffffu, s1v[j], 16);
        s2v[j] += __shfl_xor_sync(0xffffffffu, s2v[j], 8);
        s2v[j] += __shfl_xor_sync(0xffffffffu, s2v[j], 16);
    }
    if (lane < 8) {
        int cib = (lane * 4) & 31;
        #pragma unroll
        for (int j = 0; j < 4; j++) {
            atomicAdd(s_gn + cib + j, s1v[j]);
            atomicAdd(s_gn + 32 + cib + j, s2v[j]);
        }
    }

    int hl = wid >> 1;            // output row within tile (0..3)
    int wbase = (wid & 1) * 32;   // col base of this warp's 32-pixel strip
    int g = lane >> 2;
    int t = lane & 3;

    const u32 inh_a = smb + SM_INH;
    const u32 wh_a  = smb + SM_WH;
    const u32 alane = (u32)((lane & 15) * 80 + (lane >> 4) * 16);
    const u32 blane = (u32)(((lane >> 4) * 8 + (lane & 7)) * 656 + ((lane >> 3) & 1) * 16);

    float acc[2][4][4];
    for (int m = 0; m < 2; m++)
        for (int n = 0; n < 4; n++)
            for (int r = 0; r < 4; r++) acc[m][n][r] = 0.f;

    for (int tap = 0; tap < 9; tap++) {
        int kh = tap / 3;
        int kw = tap - kh*3;
        u32 apix = inh_a + (u32)(((hl + kh)*66 + wbase + kw) * 80) + alane;
        u32 wtap = wh_a + blane + (u32)(tap * 64);
        #pragma unroll
        for (int c = 0; c < 2; c++) {
            u32 aoff = apix + (u32)(c * 32);
            u32 boff = wtap + (u32)(c * 32);
            u32 ah0[4], ah1[4];
            ldsm_x4(ah0, aoff);
            ldsm_x4(ah1, aoff + 1280u);
            u32 bh[2][4];
            ldsm_x4(bh[0], boff);
            ldsm_x4(bh[1], boff + 10496u);
            #pragma unroll
            for (int n = 0; n < 4; n++) {
                const u32* Bh = &bh[n >> 1][(n & 1) * 2];
                mma_f16(acc[0][n], ah0, Bh);
                mma_f16(acc[1][n], ah1, Bh);
            }
        }
    }
    // all input-plane reads done before s_out alias is written
    __syncthreads();

    // stage D to smem: s_out[pix_in_tile * 34 + ch]
    #pragma unroll
    for (int m = 0; m < 2; m++) {
        #pragma unroll
        for (int n = 0; n < 4; n++) {
            int pix0 = hl*64 + wbase + m*16 + g;
            int ch = n*8 + 2*t;
            s_out[pix0*34 + ch]       = acc[m][n][0];
            s_out[pix0*34 + ch + 1]   = acc[m][n][1];
            s_out[(pix0+8)*34 + ch]   = acc[m][n][2];
            s_out[(pix0+8)*34 + ch+1] = acc[m][n][3];
        }
    }
    __syncwarp();

    // x2 write as fp16 (+b3) + channel sums from fp32 (lane = channel)
    float b3v = b3[lane];
    float csum = 0.f;
    int hglob = h0 + hl;
    for (int j2 = 0; j2 < 32; j2++) {
        int pix = hl*64 + wbase + j2;
        float v = s_out[pix*34 + lane] + b3v;
        g_x2h[((size_t)gimg*4096 + (size_t)hglob*64 + wbase + j2)*32 + lane] = __float2half_rn(v);
        csum += v;
    }

    s_red[wid*32 + lane] = csum;
    __syncthreads();
    if (wid == 0) {
        float tsum = 0.f;
        for (int k = 0; k < 8; k++) tsum += s_red[k*32 + lane];
        atomicAdd(g_colsum + gimg*32 + lane, tsum);
    } else if (wid == 1) {
        atomicAdd(g_sum + gimg*32 + lane, s_gn[lane]);
    } else if (wid == 2) {
        atomicAdd(g_sumsq + gimg*32 + lane, s_gn[32 + lane]);
    }
}

// ===================== K3: mu/rsqrt, softmax(x21), softmax(gn_beta)=x11 =====================
__global__ void k3_finalize(const float* __restrict__ gn_beta) {
    int g = blockIdx.x;
    int t = threadIdx.x;
    float mu  = g_sum[g*32 + t] * (1.f/4096.f);
    float var = g_sumsq[g*32 + t] * (1.f/4096.f) - mu*mu;
    g_mu[g*32 + t] = mu;
    g_rs[g*32 + t] = rsqrtf(var + 1e-3f);

    float m = g_colsum[g*32 + t] * (1.f/4096.f);
    float mx = m;
    for (int o = 16; o > 0; o >>= 1) mx = fmaxf(mx, __shfl_xor_sync(0xffffffffu, mx, o));
    float e = expf(m - mx);
    float se = e;
    for (int o = 16; o > 0; o >>= 1) se += __shfl_xor_sync(0xffffffffu, se, o);
    g_x21[g*32 + t] = e / se;

    if (g == 0) {
        float bb = gn_beta[t];
        float mx2 = bb;
        for (int o = 16; o > 0; o >>= 1) mx2 = fmaxf(mx2, __shfl_xor_sync(0xffffffffu, mx2, o));
        float e2 = expf(bb - mx2);
        float s2 = e2;
        for (int o = 16; o > 0; o >>= 1) s2 += __shfl_xor_sync(0xffffffffu, s2, o);
        g_x11[t] = e2 / s2;
    }
}

// ===================== K4: weights (flat einsum) + sigmoid + output =====================
__global__ void __launch_bounds__(1024) k4_weights_out(const float* __restrict__ x,
                                                       const float* __restrict__ gn_gamma,
                                                       const float* __restrict__ gn_beta,
                                                       float* __restrict__ out) {
    int g = blockIdx.x;
    int tid = threadIdx.x;
    const float* A   = x     + (size_t)g * IMG_ELEMS;
    const __half* X2 = g_x2h + (size_t)g * IMG_ELEMS;
    __shared__ float s_wt[4096];
    __shared__ float s_sh[2048];
    __shared__ float s_sw[2048];
    __shared__ float s_x11[32];
    __shared__ float s_x21[32];
    __shared__ float s_mu[32];
    __shared__ float s_rs[32];
    __shared__ float s_gb[64];
    for (int i = tid; i < 2048; i += 1024) {
        s_sh[i] = g_sh[g*2048 + i];
        s_sw[i] = g_sw[g*2048 + i];
    }
    if (tid < 32) {
        s_x11[tid] = g_x11[tid];
        s_x21[tid] = g_x21[g*32 + tid];
        s_mu[tid]  = g_mu[g*32 + tid];
        s_rs[tid]  = g_rs[g*32 + tid];
        s_gb[tid]      = gn_gamma[tid];
        s_gb[32 + tid] = gn_beta[tid];
    }
    __syncthreads();

    for (int k = 0; k < 4; k++) {
        int l  = tid + k*1024;
        int cc = l & 31;
        int q  = l >> 5;
        int w  = q & 63;
        float rs = s_rs[cc];
        float mu = s_mu[cc];
        float gam = s_gb[cc];
        float bet = s_gb[32 + cc];
        float swv = s_sw[w*32 + cc];
        float acc = 0.f;
        for (int c = 0; c < 32; c++) {
            int f = c*4096 + l;
            float x2v = __half2float(X2[f]);
            float a   = A[f];
            int h = 2*c + (q >> 6);
            float gt  = a * s_sh[h*32 + cc] * swv;
            float x1v = (gt - mu) * rs * gam + bet;
            acc += s_x11[c]*x2v + s_x21[c]*x1v;
        }
        s_wt[l] = 1.f / (1.f + expf(-acc));
    }
    __syncthreads();

    const float4* A4 = (const float4*)A;
    float4* O4 = (float4*)(out + (size_t)g * IMG_ELEMS);
    for (int i = tid; i < IMG_ELEMS/4; i += 1024) {
        float sg = s_wt[i >> 3];
        float4 a4 = A4[i];
        float4 o;
        o.x = a4.x*sg;
        o.y = a4.y*sg;
        o.z = a4.z*sg;
        o.w = a4.w*sg;
        O4[i] = o;
    }
}

// ===================== launch =====================
extern "C" void kernel_launch(void* const* d_in, const int* in_sizes, int n_in,
                              void* d_out, int out_size) {
    const float* x     = (const float*)d_in[0];
    const float* w1    = (const float*)d_in[1];
    const float* b1    = (const float*)d_in[2];
    const float* w3    = (const float*)d_in[3];
    const float* b3    = (const float*)d_in[4];
    const float* gamma = (const float*)d_in[5];
    const float* beta  = (const float*)d_in[6];
    float* out = (float*)d_out;

    cudaFuncSetAttribute(k2_conv, cudaFuncAttributeMaxDynamicSharedMemorySize, SM_TOTAL);

    k0_prep<<<1, 256>>>(w3);
    k1_means<<<NIMG, 256>>>(x, w1, b1);
    k2_conv<<<dim3(16, NIMG), 256, SM_TOTAL>>>(x, b3);
    k3_finalize<<<NIMG, 32>>>(beta);
    k4_weights_out<<<NIMG, 1024>>>(x, gamma, beta, out);
}

// round 14
// speedup vs baseline: 2.4390x; 1.0926x over previous
#include <cuda_runtime.h>
#include <cuda_fp16.h>
#include <cstdint>
#include <math.h>

typedef unsigned int u32;

#define NIMG 512
#define IMG_ELEMS (64*64*32)

// ---- scratch (device globals; allocation-free rule) ----
__device__ __half g_x2h[67108864];      // conv output (+b3), fp16
__device__ float g_sh[NIMG*64*32];
__device__ float g_sw[NIMG*64*32];
__device__ float g_sum[NIMG*32];
__device__ float g_sumsq[NIMG*32];
__device__ float g_colsum[NIMG*32];
__device__ float g_mu[NIMG*32];
__device__ float g_rs[NIMG*32];
__device__ float g_x21[NIMG*32];
__device__ float g_x11[32];
// W transposed [d][k], fp16, row stride 328 halves (=656 B; ldmatrix conflict-free)
__device__ __align__(16) unsigned short g_whi[32*328];

// m16n8k16 row.col fp16 -> f32 accumulate (HMMA.16816; valid on base sm_103)
__device__ __forceinline__ void mma_f16(float* c, const u32* a, const u32* b) {
    asm volatile("mma.sync.aligned.m16n8k16.row.col.f32.f16.f16.f32 {%0,%1,%2,%3}, {%4,%5,%6,%7}, {%8,%9}, {%0,%1,%2,%3};" : "+f"(c[0]), "+f"(c[1]), "+f"(c[2]), "+f"(c[3]) : "r"(a[0]), "r"(a[1]), "r"(a[2]), "r"(a[3]), "r"(b[0]), "r"(b[1]));
}
__device__ __forceinline__ void ldsm_x4(u32* r, u32 saddr) {
    asm volatile("ldmatrix.sync.aligned.m8n8.x4.shared.b16 {%0,%1,%2,%3}, [%4];" : "=r"(r[0]), "=r"(r[1]), "=r"(r[2]), "=r"(r[3]) : "r"(saddr));
}
__device__ __forceinline__ u32 smem_u32(const void* p) {
    u32 a;
    asm("{ .reg .u64 t; cvta.to.shared.u64 t, %1; cvt.u32.u64 %0, t; }" : "=r"(a) : "l"(p));
    return a;
}

// ===================== K0: transpose conv weights to fp16 =====================
__global__ void k0_prep(const float* __restrict__ w3) {
    for (int idx = threadIdx.x; idx < 32*328; idx += blockDim.x) {
        int d = idx / 328;
        int k = idx % 328;
        float v = (k < 288) ? w3[k*32 + d] : 0.f;
        __half hb = __float2half_rn(v);
        g_whi[idx] = *(unsigned short*)&hb;
    }
}

// ===================== K1: row/col means + 32x32 matmul + sigmoid (+ zero stats) =====================
__global__ void __launch_bounds__(256) k1_means(const float* __restrict__ x,
                                                const float* __restrict__ w1,
                                                const float* __restrict__ b1) {
    int g = blockIdx.x;
    const float* A = x + (size_t)g * IMG_ELEMS;
    __shared__ float s_xh[2048];
    __shared__ float s_xw[2048];
    __shared__ float s_w1[1024];
    int tid = threadIdx.x;
    int lane = tid & 31;
    int wid = tid >> 5;

    if (tid < 32) {
        g_sum[g*32+tid] = 0.f;
        g_sumsq[g*32+tid] = 0.f;
        g_colsum[g*32+tid] = 0.f;
    }
    for (int i = tid; i < 1024; i += 256) s_w1[i] = w1[i];

    for (int h = wid; h < 64; h += 8) {
        float acc = 0.f;
        for (int w = 0; w < 64; w++) acc += A[(h*64 + w)*32 + lane];
        s_xh[h*32 + lane] = acc * (1.f/64.f);
    }
    for (int w = wid; w < 64; w += 8) {
        float acc = 0.f;
        for (int h = 0; h < 64; h++) acc += A[(h*64 + w)*32 + lane];
        s_xw[w*32 + lane] = acc * (1.f/64.f);
    }
    __syncthreads();
    for (int i = tid; i < 4096; i += 256) {
        int row = i >> 5;
        int d = i & 31;
        const float* v = (row < 64) ? (s_xh + row*32) : (s_xw + (row-64)*32);
        float acc = b1[d];
        for (int c = 0; c < 32; c++) acc = fmaf(v[c], s_w1[c*32 + d], acc);
        float s = 1.f / (1.f + expf(-acc));
        if (row < 64) g_sh[(g*64 + row)*32 + d] = s;
        else g_sw[(g*64 + (row-64))*32 + d] = s;
    }
}

// ===================== K2: fp16 HMMA conv, stats fused into fill =====================
// Block: 4 output rows x 64 cols x 32ch. 8 warps; warp = 32-pixel strip.
// s_out stride 33 -> smem 56064 B -> 4 CTAs/SM. Fill loop r-outer (no int division).
#define SM_WH  0
#define SM_INH 20992
#define SM_RED 54784
#define SM_GN  55808
#define SM_TOTAL 56064
// input plane: [6 rows][66 cols][32 ci fp16], col stride 20 u32 (80 B); 31680 B
// s_out alias: 256 px * 33 f32 = 33792 B (region is max of the two)

__global__ void __launch_bounds__(256, 4) k2_conv(const float* __restrict__ x,
                                                  const float* __restrict__ b3) {
    int gimg = blockIdx.y;
    int h0 = blockIdx.x * 4;
    const float* A = x + (size_t)gimg * IMG_ELEMS;
    extern __shared__ char sm[];
    u32 smb = smem_u32(sm);
    u32* inh32 = (u32*)(sm + SM_INH);
    float* s_out = (float*)(sm + SM_INH);   // alias: valid only after all input reads; 33792 B
    float* s_red = (float*)(sm + SM_RED);
    float* s_gn  = (float*)(sm + SM_GN);    // [0..31] sum, [32..63] sumsq
    int tid = threadIdx.x;
    int lane = tid & 31;
    int wid = tid >> 5;

    if (tid < 64) s_gn[tid] = 0.f;
    // load W plane (pre-transposed fp16): 20992 B
    {
        const float4* srcH = (const float4*)g_whi;
        float4* dstH = (float4*)(sm + SM_WH);
        for (int i = tid; i < 1312; i += 256) dstH[i] = srcH[i];
    }

    // fill halo input tile (rows h0-1 .. h0+4) fp16; gated GN stats from fp32 inline.
    // ci base loop-invariant: (tid&7)*4. No integer division (r outer, col = j>>3).
    float s1v[4] = {0.f, 0.f, 0.f, 0.f};
    float s2v[4] = {0.f, 0.f, 0.f, 0.f};
    for (int r = 0; r < 6; r++) {
        int h = h0 - 1 + r;
        bool hok = (h >= 0 && h < 64);
        for (int j = tid; j < 528; j += 256) {     // 66 cols x 8 ci-chunks
            int col = j >> 3;
            int ci = (j & 7) * 4;
            bool inb = hok && col >= 1 && col <= 64;
            float4 v = make_float4(0.f, 0.f, 0.f, 0.f);
            if (inb) v = *(const float4*)(A + (h*64 + col - 1)*32 + ci);
            __half2 p01 = __floats2half2_rn(v.x, v.y);
            __half2 p23 = __floats2half2_rn(v.z, v.w);
            int wb = (r*66 + col)*20 + (ci >> 1);
            inh32[wb]     = *(u32*)&p01;
            inh32[wb + 1] = *(u32*)&p23;
            if (inb && r >= 1 && r <= 4) {
                float4 shv = *(const float4*)(g_sh + (gimg*64 + h)*32 + ci);
                float4 swv = *(const float4*)(g_sw + (gimg*64 + col - 1)*32 + ci);
                float g0 = v.x * shv.x * swv.x;
                float g1 = v.y * shv.y * swv.y;
                float g2 = v.z * shv.z * swv.z;
                float g3 = v.w * shv.w * swv.w;
                s1v[0] += g0; s2v[0] += g0*g0;
                s1v[1] += g1; s2v[1] += g1*g1;
                s1v[2] += g2; s2v[2] += g2*g2;
                s1v[3] += g3; s2v[3] += g3*g3;
            }
        }
    }
    __syncthreads();

    // reduce gated stats: lanes {l, l^8, l^16, l^24} share the same ci base
    #pragma unroll
    for (int j = 0; j < 4; j++) {
        s1v[j] += __shfl_xor_sync(0xffffffffu, s1v[j], 8);
        s1v[j] += __shfl_xor_sync(0xffffffffu, s1v[j], 16);
        s2v[j] += __shfl_xor_sync(0xffffffffu, s2v[j], 8);
        s2v[j] += __shfl_xor_sync(0xffffffffu, s2v[j], 16);
    }
    if (lane < 8) {
        int cib = (lane & 7) * 4;
        #pragma unroll
        for (int j = 0; j < 4; j++) {
            atomicAdd(s_gn + cib + j, s1v[j]);
            atomicAdd(s_gn + 32 + cib + j, s2v[j]);
        }
    }

    int hl = wid >> 1;            // output row within tile (0..3)
    int wbase = (wid & 1) * 32;   // col base of this warp's 32-pixel strip
    int g = lane >> 2;
    int t = lane & 3;

    const u32 inh_a = smb + SM_INH;
    const u32 wh_a  = smb + SM_WH;
    const u32 alane = (u32)((lane & 15) * 80 + (lane >> 4) * 16);
    const u32 blane = (u32)(((lane >> 4) * 8 + (lane & 7)) * 656 + ((lane >> 3) & 1) * 16);

    float acc[2][4][4];
    for (int m = 0; m < 2; m++)
        for (int n = 0; n < 4; n++)
            for (int r = 0; r < 4; r++) acc[m][n][r] = 0.f;

    for (int tap = 0; tap < 9; tap++) {
        int kh = tap / 3;
        int kw = tap - kh*3;
        u32 apix = inh_a + (u32)(((hl + kh)*66 + wbase + kw) * 80) + alane;
        u32 wtap = wh_a + blane + (u32)(tap * 64);
        #pragma unroll
        for (int c = 0; c < 2; c++) {
            u32 aoff = apix + (u32)(c * 32);
            u32 boff = wtap + (u32)(c * 32);
            u32 ah0[4], ah1[4];
            ldsm_x4(ah0, aoff);
            ldsm_x4(ah1, aoff + 1280u);
            u32 bh[2][4];
            ldsm_x4(bh[0], boff);
            ldsm_x4(bh[1], boff + 10496u);
            #pragma unroll
            for (int n = 0; n < 4; n++) {
                const u32* Bh = &bh[n >> 1][(n & 1) * 2];
                mma_f16(acc[0][n], ah0, Bh);
                mma_f16(acc[1][n], ah1, Bh);
            }
        }
    }
    // all input-plane reads done before s_out alias is written
    __syncthreads();

    // stage D to smem: s_out[pix_in_tile * 33 + ch]
    #pragma unroll
    for (int m = 0; m < 2; m++) {
        #pragma unroll
        for (int n = 0; n < 4; n++) {
            int pix0 = hl*64 + wbase + m*16 + g;
            int ch = n*8 + 2*t;
            s_out[pix0*33 + ch]       = acc[m][n][0];
            s_out[pix0*33 + ch + 1]   = acc[m][n][1];
            s_out[(pix0+8)*33 + ch]   = acc[m][n][2];
            s_out[(pix0+8)*33 + ch+1] = acc[m][n][3];
        }
    }
    __syncwarp();

    // x2 write as fp16 (+b3) + channel sums from fp32 (lane = channel)
    float b3v = b3[lane];
    float csum = 0.f;
    int hglob = h0 + hl;
    for (int j2 = 0; j2 < 32; j2++) {
        int pix = hl*64 + wbase + j2;
        float v = s_out[pix*33 + lane] + b3v;
        g_x2h[((size_t)gimg*4096 + (size_t)hglob*64 + wbase + j2)*32 + lane] = __float2half_rn(v);
        csum += v;
    }

    s_red[wid*32 + lane] = csum;
    __syncthreads();
    if (wid == 0) {
        float tsum = 0.f;
        for (int k = 0; k < 8; k++) tsum += s_red[k*32 + lane];
        atomicAdd(g_colsum + gimg*32 + lane, tsum);
    } else if (wid == 1) {
        atomicAdd(g_sum + gimg*32 + lane, s_gn[lane]);
    } else if (wid == 2) {
        atomicAdd(g_sumsq + gimg*32 + lane, s_gn[32 + lane]);
    }
}

// ===================== K3: mu/rsqrt, softmax(x21), softmax(gn_beta)=x11 =====================
__global__ void k3_finalize(const float* __restrict__ gn_beta) {
    int g = blockIdx.x;
    int t = threadIdx.x;
    float mu  = g_sum[g*32 + t] * (1.f/4096.f);
    float var = g_sumsq[g*32 + t] * (1.f/4096.f) - mu*mu;
    g_mu[g*32 + t] = mu;
    g_rs[g*32 + t] = rsqrtf(var + 1e-3f);

    float m = g_colsum[g*32 + t] * (1.f/4096.f);
    float mx = m;
    for (int o = 16; o > 0; o >>= 1) mx = fmaxf(mx, __shfl_xor_sync(0xffffffffu, mx, o));
    float e = expf(m - mx);
    float se = e;
    for (int o = 16; o > 0; o >>= 1) se += __shfl_xor_sync(0xffffffffu, se, o);
    g_x21[g*32 + t] = e / se;

    if (g == 0) {
        float bb = gn_beta[t];
        float mx2 = bb;
        for (int o = 16; o > 0; o >>= 1) mx2 = fmaxf(mx2, __shfl_xor_sync(0xffffffffu, mx2, o));
        float e2 = expf(bb - mx2);
        float s2 = e2;
        for (int o = 16; o > 0; o >>= 1) s2 += __shfl_xor_sync(0xffffffffu, s2, o);
        g_x11[t] = e2 / s2;
    }
}

// ===================== K4: weights (flat einsum) + sigmoid + output =====================
__global__ void __launch_bounds__(1024) k4_weights_out(const float* __restrict__ x,
                                                       const float* __restrict__ gn_gamma,
                                                       const float* __restrict__ gn_beta,
                                                       float* __restrict__ out) {
    int g = blockIdx.x;
    int tid = threadIdx.x;
    const float* A   = x     + (size_t)g * IMG_ELEMS;
    const __half* X2 = g_x2h + (size_t)g * IMG_ELEMS;
    __shared__ float s_wt[4096];
    __shared__ float s_sh[2048];
    __shared__ float s_sw[2048];
    __shared__ float s_x11[32];
    __shared__ float s_x21[32];
    __shared__ float s_mu[32];
    __shared__ float s_rs[32];
    __shared__ float s_gb[64];
    for (int i = tid; i < 2048; i += 1024) {
        s_sh[i] = g_sh[g*2048 + i];
        s_sw[i] = g_sw[g*2048 + i];
    }
    if (tid < 32) {
        s_x11[tid] = g_x11[tid];
        s_x21[tid] = g_x21[g*32 + tid];
        s_mu[tid]  = g_mu[g*32 + tid];
        s_rs[tid]  = g_rs[g*32 + tid];
        s_gb[tid]      = gn_gamma[tid];
        s_gb[32 + tid] = gn_beta[tid];
    }
    __syncthreads();

    for (int k = 0; k < 4; k++) {
        int l  = tid + k*1024;
        int cc = l & 31;
        int q  = l >> 5;
        int w  = q & 63;
        float rs = s_rs[cc];
        float mu = s_mu[cc];
        float gam = s_gb[cc];
        float bet = s_gb[32 + cc];
        float swv = s_sw[w*32 + cc];
        float acc = 0.f;
        for (int c = 0; c < 32; c++) {
            int f = c*4096 + l;
            float x2v = __half2float(X2[f]);
            float a   = A[f];
            int h = 2*c + (q >> 6);
            float gt  = a * s_sh[h*32 + cc] * swv;
            float x1v = (gt - mu) * rs * gam + bet;
            acc += s_x11[c]*x2v + s_x21[c]*x1v;
        }
        s_wt[l] = 1.f / (1.f + expf(-acc));
    }
    __syncthreads();

    const float4* A4 = (const float4*)A;
    float4* O4 = (float4*)(out + (size_t)g * IMG_ELEMS);
    for (int i = tid; i < IMG_ELEMS/4; i += 1024) {
        float sg = s_wt[i >> 3];
        float4 a4 = A4[i];
        float4 o;
        o.x = a4.x*sg;
        o.y = a4.y*sg;
        o.z = a4.z*sg;
        o.w = a4.w*sg;
        O4[i] = o;
    }
}

// ===================== launch =====================
extern "C" void kernel_launch(void* const* d_in, const int* in_sizes, int n_in,
                              void* d_out, int out_size) {
    const float* x     = (const float*)d_in[0];
    const float* w1    = (const float*)d_in[1];
    const float* b1    = (const float*)d_in[2];
    const float* w3    = (const float*)d_in[3];
    const float* b3    = (const float*)d_in[4];
    const float* gamma = (const float*)d_in[5];
    const float* beta  = (const float*)d_in[6];
    float* out = (float*)d_out;

    cudaFuncSetAttribute(k2_conv, cudaFuncAttributeMaxDynamicSharedMemorySize, SM_TOTAL);

    k0_prep<<<1, 256>>>(w3);
    k1_means<<<NIMG, 256>>>(x, w1, b1);
    k2_conv<<<dim3(16, NIMG), 256, SM_TOTAL>>>(x, b3);
    k3_finalize<<<NIMG, 32>>>(beta);
    k4_weights_out<<<NIMG, 1024>>>(x, gamma, beta, out);
}